// round 11
// baseline (speedup 1.0000x reference)
#include <cuda_runtime.h>
#include <cuda_fp16.h>
#include <math.h>
#include <stdint.h>

#define SEQ     2048
#define HIDDEN  2048
#define HD      128
#define NH      16
#define NKV     2

// ---------------- scratch (device globals) ----------------
__device__ __align__(16) __half g_qh [(size_t)NH  * SEQ * HD];
__device__ __align__(16) __half g_kh [(size_t)NKV * SEQ * HD];
__device__ __align__(16) __half g_vth[(size_t)NKV * HD * SEQ];
__device__ __align__(16) __half g_ah [(size_t)NH  * SEQ * HD];
__device__ __align__(16) float2 g_tab[(size_t)SEQ * 64];
#define QW_OFF 0
#define KW_OFF 4194304
#define VW_OFF 4718592
#define OW_OFF 5242880
#define W_TOT  9437184
__device__ __align__(16) __half g_wh[W_TOT];

// ================= helpers =================
__device__ __forceinline__ uint32_t smem_u32(const void* p) {
    uint32_t a;
    asm("{ .reg .u64 t; cvta.to.shared.u64 t, %1; cvt.u32.u64 %0, t; }" : "=r"(a) : "l"(p));
    return a;
}

#define LDSM4(r0, r1, r2, r3, addr) \
    asm volatile("ldmatrix.sync.aligned.m8n8.x4.shared.b16 {%0,%1,%2,%3}, [%4];" \
                 : "=r"(r0), "=r"(r1), "=r"(r2), "=r"(r3) : "r"(addr))

#define MMA16816(c, a, b) \
    asm volatile("mma.sync.aligned.m16n8k16.row.col.f32.f16.f16.f32 " \
                 "{%0,%1,%2,%3}, {%4,%5,%6,%7}, {%8,%9}, {%0,%1,%2,%3};" \
                 : "+f"((c)[0]), "+f"((c)[1]), "+f"((c)[2]), "+f"((c)[3]) \
                 : "r"((a)[0]), "r"((a)[1]), "r"((a)[2]), "r"((a)[3]), \
                   "r"((b)[0]), "r"((b)[1]))

#define CPA16(dst, src) \
    asm volatile("cp.async.cg.shared.global [%0], [%1], 16;" :: "r"(dst), "l"(src))
#define CPA_COMMIT()  asm volatile("cp.async.commit_group;")
#define CPA_WAIT0()   asm volatile("cp.async.wait_group 0;")
#define CPA_WAIT1()   asm volatile("cp.async.wait_group 1;")

// ================= fused Q/K/V projection: M-tile 64, K-chunk 32 =================
// per-buffer smem: AH [0,5120), BH [5120,15360); double buffered
#define ROWB   80
#define ATILE  5120
#define PBUF   15360
#define PSMB   (2 * PBUF)

__device__ __forceinline__ void cvt_hi8(const float* __restrict__ xs,
                                        uint32_t* __restrict__ hw)
{
#pragma unroll
    for (int q = 0; q < 4; q++) {
        __half2 h = __floats2half2_rn(xs[2 * q], xs[2 * q + 1]);
        hw[q] = *reinterpret_cast<uint32_t*>(&h);
    }
}

// z<NH: Q head -> rope -> g_qh; z<NH+NKV: K -> rope -> g_kh; else V -> transpose -> g_vth.
__global__ __launch_bounds__(256, 2)
void proj_k(const float* __restrict__ qhid, const float* __restrict__ khid,
            const float* __restrict__ vhid, const __half* __restrict__ wh,
            const float2* __restrict__ tab)
{
    extern __shared__ char dsm[];
    const int tid  = threadIdx.x;
    const int wid  = tid >> 5;
    const int lane = tid & 31;
    const int wm   = (wid >> 2) << 5;
    const int wn16 = (wid & 3) << 4;
    const int zorig = blockIdx.z;
    const int m0   = blockIdx.y << 6;

    const float*  A;
    const __half* B;
    if (zorig < NH)            { A = qhid + (long)zorig * SEQ * HIDDEN; B = wh + QW_OFF; }
    else if (zorig < NH + NKV) { A = khid + (long)(zorig - NH) * SEQ * HIDDEN; B = wh + KW_OFF + (long)(zorig - NH) * HD * HIDDEN; }
    else                       { A = vhid + (long)(zorig - NH - NKV) * SEQ * HIDDEN; B = wh + VW_OFF + (long)(zorig - NH - NKV) * HD * HIDDEN; }
    if (zorig < NH) B += (long)zorig * HD * HIDDEN;
    A += (long)m0 * HIDDEN;

    float acc[2][4][4];
#pragma unroll
    for (int i = 0; i < 2; i++)
#pragma unroll
        for (int j = 0; j < 4; j++)
#pragma unroll
            for (int q = 0; q < 4; q++) acc[i][j][q] = 0.f;

    const uint32_t smbase = smem_u32(dsm);
    const int a_row  = wm + (lane & 15);
    const int a_koff = (lane >> 4) << 4;
    const int brow   = (lane & 7) + ((lane >> 4) & 1) * 8;
    const int b_koff = ((lane >> 3) & 1) << 4;

    const int arow = tid >> 2, aunit = tid & 3;
    const int asoff = arow * ROWB + aunit * 16;
    const int br_   = tid >> 1, bhalf = tid & 1;
    const uint32_t bcp_off = ATILE + (uint32_t)br_ * ROWB + (uint32_t)bhalf * 32;
    const long     bcp_src = (long)br_ * HIDDEN + bhalf * 16;

    float ra[8];
    {
        CPA16(smbase + bcp_off,      B + bcp_src);
        CPA16(smbase + bcp_off + 16, B + bcp_src + 8);
        const float4* pa = (const float4*)(A + (long)arow * HIDDEN + aunit * 8);
        *(float4*)(ra)     = __ldcs(pa);
        *(float4*)(ra + 4) = __ldcs(pa + 1);
        uint32_t hw[4];
        cvt_hi8(ra, hw);
        *(uint4*)(dsm + asoff) = make_uint4(hw[0], hw[1], hw[2], hw[3]);
        CPA_COMMIT();
        CPA_WAIT0();
    }
    __syncthreads();

    for (int i = 0; i < 64; i++) {
        if (i + 1 < 64) {
            const int k0 = (i + 1) << 5;
            const uint32_t bb = smbase + ((i + 1) & 1) * PBUF;
            CPA16(bb + bcp_off,      B + k0 + bcp_src);
            CPA16(bb + bcp_off + 16, B + k0 + bcp_src + 8);
            const float4* pa = (const float4*)(A + (long)arow * HIDDEN + k0 + aunit * 8);
            *(float4*)(ra)     = __ldcs(pa);
            *(float4*)(ra + 4) = __ldcs(pa + 1);
            CPA_COMMIT();
        }
        const uint32_t tb = smbase + (i & 1) * PBUF;
#pragma unroll
        for (int ks = 0; ks < 2; ks++) {
            uint32_t bh[4][2];
            const uint32_t ka = ks * 32 + a_koff;
            const uint32_t kb = ks * 32 + b_koff;
#pragma unroll
            for (int p = 0; p < 2; p++) {
                uint32_t r0, r1, r2, r3;
                LDSM4(r0, r1, r2, r3,
                      tb + ATILE + (uint32_t)(wn16 + p * 64 + brow) * ROWB + kb);
                bh[2 * p][0] = r0; bh[2 * p][1] = r1;
                bh[2 * p + 1][0] = r2; bh[2 * p + 1][1] = r3;
            }
#pragma unroll
            for (int mi = 0; mi < 2; mi++) {
                uint32_t ah[4];
                LDSM4(ah[0], ah[1], ah[2], ah[3],
                      tb + (uint32_t)(a_row + mi * 16) * ROWB + ka);
#pragma unroll
                for (int ni = 0; ni < 4; ni++) MMA16816(acc[mi][ni], ah, bh[ni]);
            }
        }
        if (i + 1 < 64) {
            char* buf = dsm + ((i + 1) & 1) * PBUF;
            uint32_t hw[4];
            cvt_hi8(ra, hw);
            *(uint4*)(buf + asoff) = make_uint4(hw[0], hw[1], hw[2], hw[3]);
            CPA_WAIT0();
        }
        __syncthreads();
    }

    // ---------------- epilogue ----------------
    const int g = lane >> 2, t = lane & 3;

    if (zorig < NH + NKV) {
        __half* dst = (zorig < NH)
            ? (g_qh + (long)zorig * SEQ * HD)
            : (g_kh + (long)(zorig - NH) * SEQ * HD);
#pragma unroll
        for (int mi = 0; mi < 2; mi++) {
            const int l0 = m0 + wm + mi * 16 + g;
#pragma unroll
            for (int pr = 0; pr < 2; pr++) {
                const int i0 = wn16 + pr * 8 + t * 2;
#pragma unroll
                for (int rr = 0; rr < 2; rr++) {
                    const int l = l0 + rr * 8;
                    const int e = rr * 2;
                    const float2 cs0 = tab[l * 64 + i0];
                    const float2 cs1 = tab[l * 64 + i0 + 1];
                    const float x1a = acc[mi][pr][e],     x1b = acc[mi][pr][e + 1];
                    const float x2a = acc[mi][pr + 2][e], x2b = acc[mi][pr + 2][e + 1];
                    *(__half2*)(dst + (long)l * HD + i0) =
                        __floats2half2_rn(x1a * cs0.x - x2a * cs0.y,
                                          x1b * cs1.x - x2b * cs1.y);
                    *(__half2*)(dst + (long)l * HD + i0 + 64) =
                        __floats2half2_rn(x2a * cs0.x + x1a * cs0.y,
                                          x2b * cs1.x + x1b * cs1.y);
                }
            }
        }
    } else {
        __half* sm = (__half*)dsm;
#pragma unroll
        for (int mi = 0; mi < 2; mi++) {
            const int r0 = wm + mi * 16 + g;
#pragma unroll
            for (int ni = 0; ni < 4; ni++) {
                const int cc = wn16 + (ni >> 1) * 64 + (ni & 1) * 8 + t * 2;
                sm[cc * 72 + r0]           = __float2half_rn(acc[mi][ni][0]);
                sm[(cc + 1) * 72 + r0]     = __float2half_rn(acc[mi][ni][1]);
                sm[cc * 72 + r0 + 8]       = __float2half_rn(acc[mi][ni][2]);
                sm[(cc + 1) * 72 + r0 + 8] = __float2half_rn(acc[mi][ni][3]);
            }
        }
        __syncthreads();
        __half* dst = g_vth + (long)(zorig - NH - NKV) * HD * SEQ;
        const int col = tid >> 1, rh = (tid & 1) << 5;
        const __half* src = sm + col * 72 + rh;
        __half* gp = dst + (long)col * SEQ + m0 + rh;
#pragma unroll
        for (int q = 0; q < 4; q++)
            *(uint4*)(gp + q * 8) = *(const uint4*)(src + q * 8);
    }
}

// ================= O projection: one-shot K=128, smem-staged coalesced store =================
// loads: A [0,34816), B [34816,69632) (272B rows). after compute, smem reused as
// fp32 output stage: 128 rows x 132-float padded rows (67584 B <= 69632).
#define OROW  272
#define OASZ  34816
#define OSMB  69632
#define OPAD  132

__global__ __launch_bounds__(256, 2)
void oproj_k(const __half* __restrict__ ahh, const __half* __restrict__ whO,
             float* __restrict__ out)
{
    extern __shared__ char dsm[];
    const int tid  = threadIdx.x;
    const int wid  = tid >> 5;
    const int lane = tid & 31;
    const int wm   = (wid >> 2) << 6;
    const int wn   = (wid & 3) << 5;
    const int z    = blockIdx.z;
    const int m0   = blockIdx.y << 7;
    const int n0   = blockIdx.x << 7;

    const __half* A = ahh + ((long)z * SEQ + m0) * HD;
    const __half* B = whO + (long)n0 * HIDDEN + (long)z * HD;
    float*        C = out + (long)z * SEQ * HIDDEN;

    const uint32_t smbase = smem_u32(dsm);

#pragma unroll
    for (int i = 0; i < 8; i++) {
        const int u = tid + (i << 8);
        const int row = u >> 4, un = u & 15;
        CPA16(smbase + row * OROW + un * 16, A + (long)row * HD + un * 8);
        CPA16(smbase + OASZ + row * OROW + un * 16, B + (long)row * HIDDEN + un * 8);
    }
    CPA_COMMIT();
    CPA_WAIT0();
    __syncthreads();

    float acc[4][4][4];
#pragma unroll
    for (int i = 0; i < 4; i++)
#pragma unroll
        for (int j = 0; j < 4; j++)
#pragma unroll
            for (int q = 0; q < 4; q++) acc[i][j][q] = 0.f;

    const int a_row  = wm + (lane & 15);
    const int a_koff = (lane >> 4) << 4;
    const int brow   = (lane & 7) + ((lane >> 4) & 1) * 8;
    const int b_koff = ((lane >> 3) & 1) << 4;

#pragma unroll
    for (int ks = 0; ks < 8; ks++) {
        uint32_t bh[4][2];
        const uint32_t ka = ks * 32 + a_koff;
        const uint32_t kb = ks * 32 + b_koff;
#pragma unroll
        for (int p = 0; p < 2; p++) {
            uint32_t r0, r1, r2, r3;
            LDSM4(r0, r1, r2, r3,
                  smbase + OASZ + (uint32_t)(wn + p * 16 + brow) * OROW + kb);
            bh[2 * p][0] = r0; bh[2 * p][1] = r1;
            bh[2 * p + 1][0] = r2; bh[2 * p + 1][1] = r3;
        }
#pragma unroll
        for (int mi = 0; mi < 4; mi++) {
            uint32_t ah[4];
            LDSM4(ah[0], ah[1], ah[2], ah[3],
                  smbase + (uint32_t)(a_row + mi * 16) * OROW + ka);
#pragma unroll
            for (int ni = 0; ni < 4; ni++) MMA16816(acc[mi][ni], ah, bh[ni]);
        }
    }

    // ---- stage accumulators in smem (A/B tiles are dead now) ----
    __syncthreads();
    float* smf = (float*)dsm;
    const int g = lane >> 2, t = lane & 3;
#pragma unroll
    for (int mi = 0; mi < 4; mi++) {
        const int r0 = wm + mi * 16 + g;
#pragma unroll
        for (int ni = 0; ni < 4; ni++) {
            const int cc = wn + ni * 8 + t * 2;
            *(float2*)(smf + r0 * OPAD + cc)       = make_float2(acc[mi][ni][0], acc[mi][ni][1]);
            *(float2*)(smf + (r0 + 8) * OPAD + cc) = make_float2(acc[mi][ni][2], acc[mi][ni][3]);
        }
    }
    __syncthreads();

    // ---- coalesced streaming store: 128 rows x 32 16B-units ----
#pragma unroll
    for (int i = 0; i < 16; i++) {
        const int u = tid + (i << 8);
        const int row = u >> 5, un = u & 31;
        const float4 v = *(const float4*)(smf + row * OPAD + un * 4);
        __stcs((float4*)(C + (long)(m0 + row) * HIDDEN + n0 + un * 4), v);
    }
}

// ================= flash attention (unchanged, validated) =================
#define K_OFF  17408
#define KBUFB  17408
#define V_OFF  52224
#define VBUFB  18432
#define FSMEM  89088
#define FC     0.12751744f

__device__ __forceinline__ void kv_prefetch(uint32_t smb, int buf, int kv0,
    const __half* __restrict__ khp, const __half* __restrict__ vhp, int tid)
{
#pragma unroll
    for (int i = 0; i < 8; i++) {
        int t = tid + (i << 7);
        int unit = t & 15, row = t >> 4;
        CPA16(smb + K_OFF + buf * KBUFB + row * 272 + unit * 16,
              khp + (long)(kv0 + row) * HD + unit * 8);
    }
#pragma unroll
    for (int i = 0; i < 8; i++) {
        int t = tid + (i << 7);
        int unit = t & 7, row = t >> 3;
        CPA16(smb + V_OFF + buf * VBUFB + row * 144 + unit * 16,
              vhp + (long)row * SEQ + kv0 + unit * 8);
    }
}

__global__ __launch_bounds__(128, 2)
void flash_k(const __half* __restrict__ qhg, const __half* __restrict__ khg,
             const __half* __restrict__ vhg, __half* __restrict__ oah)
{
    extern __shared__ char dsm[];
    const uint32_t smb = smem_u32(dsm);
    const int tid  = threadIdx.x;
    const int w    = tid >> 5;
    const int lane = tid & 31;
    const int z    = blockIdx.x;
    const int mb   = 31 - blockIdx.y;
    const int kvh  = z >> 3;
    const int m0   = mb << 6;
    const int nt   = mb + 1;

    const __half* qhp = qhg + ((long)z * SEQ + m0) * HD;
    const __half* khp = khg + (long)kvh * SEQ * HD;
    const __half* vhp = vhg + (long)kvh * HD * SEQ;

#pragma unroll
    for (int i = 0; i < 8; i++) {
        int t = tid + (i << 7);
        int unit = t & 15, row = t >> 4;
        CPA16(smb + row * 272 + unit * 16, qhp + (long)row * HD + unit * 8);
    }
    CPA_COMMIT();
    kv_prefetch(smb, 0, 0, khp, vhp, tid);
    CPA_COMMIT();

    CPA_WAIT1();
    __syncthreads();
    const uint32_t qa_h = smb + (uint32_t)((w << 4) + (lane & 15)) * 272 + ((lane >> 4) << 4);
    uint32_t qf[8][4];
#pragma unroll
    for (int j = 0; j < 8; j++)
        LDSM4(qf[j][0], qf[j][1], qf[j][2], qf[j][3], qa_h + j * 32);

    float o[16][4];
#pragma unroll
    for (int nb = 0; nb < 16; nb++)
#pragma unroll
        for (int q = 0; q < 4; q++) o[nb][q] = 0.f;
    float mr0 = -1e30f, mr1 = -1e30f, l0 = 0.f, l1 = 0.f;

    const int wrow = m0 + (w << 4);
    const uint32_t brow = (lane & 7) + ((lane >> 4) & 1) * 8;
    const uint32_t bko  = ((lane >> 3) & 1) << 4;

    int buf = 0;
    for (int it = 0; it < nt; it++) {
        if (it + 1 < nt) {
            kv_prefetch(smb, buf ^ 1, (it + 1) << 6, khp, vhp, tid);
            CPA_COMMIT();
            CPA_WAIT1();
        } else {
            CPA_WAIT0();
        }
        __syncthreads();

        const int kv0 = it << 6;
        {
            const uint32_t kb_h = smb + K_OFF + buf * KBUFB;
            const uint32_t vb_h = smb + V_OFF + buf * VBUFB;

            float s[8][4];
#pragma unroll
            for (int nb = 0; nb < 8; nb++)
#pragma unroll
                for (int q = 0; q < 4; q++) s[nb][q] = 0.f;

#pragma unroll
            for (int j = 0; j < 8; j++) {
#pragma unroll
                for (int g16 = 0; g16 < 4; g16++) {
                    uint32_t bh[4];
                    const uint32_t ba = (uint32_t)(g16 * 16 + brow) * 272 + bko + j * 32;
                    LDSM4(bh[0], bh[1], bh[2], bh[3], kb_h + ba);
                    MMA16816(s[2 * g16],     qf[j], bh);
                    MMA16816(s[2 * g16 + 1], qf[j], bh + 2);
                }
            }

            const int r0 = wrow + (lane >> 2);
            const int c0 = kv0 + ((lane & 3) << 1);
            if (kv0 + 63 > wrow) {
#pragma unroll
                for (int nb = 0; nb < 8; nb++) {
                    const int c = c0 + nb * 8;
                    if (c     > r0    ) s[nb][0] = -1e30f;
                    if (c + 1 > r0    ) s[nb][1] = -1e30f;
                    if (c     > r0 + 8) s[nb][2] = -1e30f;
                    if (c + 1 > r0 + 8) s[nb][3] = -1e30f;
                }
            }

            float tm0 = -1e30f, tm1 = -1e30f;
#pragma unroll
            for (int nb = 0; nb < 8; nb++) {
                tm0 = fmaxf(tm0, fmaxf(s[nb][0], s[nb][1]));
                tm1 = fmaxf(tm1, fmaxf(s[nb][2], s[nb][3]));
            }
            tm0 = fmaxf(tm0, __shfl_xor_sync(0xffffffffu, tm0, 1));
            tm0 = fmaxf(tm0, __shfl_xor_sync(0xffffffffu, tm0, 2));
            tm1 = fmaxf(tm1, __shfl_xor_sync(0xffffffffu, tm1, 1));
            tm1 = fmaxf(tm1, __shfl_xor_sync(0xffffffffu, tm1, 2));
            const float mn0 = fmaxf(mr0, tm0), mn1 = fmaxf(mr1, tm1);
            const float sf0 = exp2f((mr0 - mn0) * FC);
            const float sf1 = exp2f((mr1 - mn1) * FC);
            mr0 = mn0; mr1 = mn1;
            l0 *= sf0;  l1 *= sf1;
#pragma unroll
            for (int nb = 0; nb < 16; nb++) {
                o[nb][0] *= sf0; o[nb][1] *= sf0;
                o[nb][2] *= sf1; o[nb][3] *= sf1;
            }
            float rs0 = 0.f, rs1 = 0.f;
#pragma unroll
            for (int nb = 0; nb < 8; nb++) {
                s[nb][0] = exp2f((s[nb][0] - mn0) * FC); rs0 += s[nb][0];
                s[nb][1] = exp2f((s[nb][1] - mn0) * FC); rs0 += s[nb][1];
                s[nb][2] = exp2f((s[nb][2] - mn1) * FC); rs1 += s[nb][2];
                s[nb][3] = exp2f((s[nb][3] - mn1) * FC); rs1 += s[nb][3];
            }
            rs0 += __shfl_xor_sync(0xffffffffu, rs0, 1);
            rs0 += __shfl_xor_sync(0xffffffffu, rs0, 2);
            rs1 += __shfl_xor_sync(0xffffffffu, rs1, 1);
            rs1 += __shfl_xor_sync(0xffffffffu, rs1, 2);
            l0 += rs0; l1 += rs1;

#pragma unroll
            for (int j = 0; j < 4; j++) {
                uint32_t pha[4];
#pragma unroll
                for (int hq = 0; hq < 4; hq++) {
                    const int nb = 2 * j + (hq >> 1);
                    const int e  = (hq & 1) << 1;
                    __half2 h = __floats2half2_rn(s[nb][e], s[nb][e + 1]);
                    pha[hq] = *reinterpret_cast<uint32_t*>(&h);
                }
#pragma unroll
                for (int g16 = 0; g16 < 8; g16++) {
                    uint32_t bh[4];
                    const uint32_t ba = (uint32_t)(g16 * 16 + brow) * 144 + bko + j * 32;
                    LDSM4(bh[0], bh[1], bh[2], bh[3], vb_h + ba);
                    MMA16816(o[2 * g16],     pha, bh);
                    MMA16816(o[2 * g16 + 1], pha, bh + 2);
                }
            }
        }
        __syncthreads();
        buf ^= 1;
    }

    const float inv0 = 1.f / l0, inv1 = 1.f / l1;
    const int r0 = wrow + (lane >> 2);
    const long base0 = ((long)z * SEQ + r0) * HD + ((lane & 3) << 1);
    const long base1 = base0 + 8 * HD;
#pragma unroll
    for (int nb = 0; nb < 16; nb++) {
        *(__half2*)(oah + base0 + nb * 8) =
            __floats2half2_rn(o[nb][0] * inv0, o[nb][1] * inv0);
        *(__half2*)(oah + base1 + nb * 8) =
            __floats2half2_rn(o[nb][2] * inv1, o[nb][3] * inv1);
    }
}

// ---------------- prep: rope table + weight cvt in one launch ----------------
#define TAB_BLKS 512
__global__ __launch_bounds__(256)
void prep_k(const int* __restrict__ pos, float2* __restrict__ tab,
            const float* __restrict__ qw, const float* __restrict__ kw,
            const float* __restrict__ vw, const float* __restrict__ ow,
            __half* __restrict__ d)
{
    const int bid = blockIdx.x;
    if (bid < TAB_BLKS) {
        int idx = bid * 256 + threadIdx.x;
        if (idx >= SEQ * 64) return;
        int i = idx & 63;
        int l = idx >> 6;
        float invf = exp2f(-(float)i * 0.31143075889569023f);
        float ang  = (float)pos[l] * invf;
        float q  = rintf(ang * 0.15915494309189535f);
        float r  = ang - q * 6.28125f;
        r        = r   - q * 1.9353071795864769e-3f;
        float s, c;
        sincosf(r, &s, &c);
        tab[idx] = make_float2(c, s);
        return;
    }
    int e = ((bid - TAB_BLKS) * 256 + threadIdx.x) << 2;
    if (e >= W_TOT) return;
    const float* s;
    if      (e < KW_OFF) s = qw + e;
    else if (e < VW_OFF) s = kw + (e - KW_OFF);
    else if (e < OW_OFF) s = vw + (e - VW_OFF);
    else                 s = ow + (e - OW_OFF);
    float4 v = *(const float4*)s;
    ((__half2*)(d + e))[0] = __floats2half2_rn(v.x, v.y);
    ((__half2*)(d + e))[1] = __floats2half2_rn(v.z, v.w);
}

// ---------------- launch ----------------
extern "C" void kernel_launch(void* const* d_in, const int* in_sizes, int n_in,
                              void* d_out, int out_size)
{
    const float* qhid = (const float*)d_in[0];
    const float* khid = (const float*)d_in[1];
    const float* vhid = (const float*)d_in[2];
    const int*   pos  = (const int*)  d_in[4];
    const float* qw   = (const float*)d_in[5];
    const float* kw   = (const float*)d_in[6];
    const float* vw   = (const float*)d_in[7];
    const float* ow   = (const float*)d_in[8];
    float*       out  = (float*)d_out;

    __half *qhh, *khh, *vth, *ahh, *wh;
    float2* tab;
    cudaGetSymbolAddress((void**)&qhh, g_qh);
    cudaGetSymbolAddress((void**)&khh, g_kh);
    cudaGetSymbolAddress((void**)&vth, g_vth);
    cudaGetSymbolAddress((void**)&ahh, g_ah);
    cudaGetSymbolAddress((void**)&wh,  g_wh);
    cudaGetSymbolAddress((void**)&tab, g_tab);

    cudaFuncSetAttribute(proj_k,  cudaFuncAttributeMaxDynamicSharedMemorySize, PSMB);
    cudaFuncSetAttribute(oproj_k, cudaFuncAttributeMaxDynamicSharedMemorySize, OSMB);
    cudaFuncSetAttribute(flash_k, cudaFuncAttributeMaxDynamicSharedMemorySize, FSMEM);

    prep_k<<<TAB_BLKS + (W_TOT / 4 + 255) / 256, 256>>>(pos, tab, qw, kw, vw, ow, wh);
    proj_k<<<dim3(1, 32, NH + 2 * NKV), 256, PSMB>>>(qhid, khid, vhid, wh, tab);
    flash_k<<<dim3(NH, 32), 128, FSMEM>>>(qhh, khh, vth, ahh);
    oproj_k<<<dim3(16, 16, NH), 256, OSMB>>>(ahh, wh + OW_OFF, out);
}

// round 12
// speedup vs baseline: 1.1317x; 1.1317x over previous
#include <cuda_runtime.h>
#include <cuda_fp16.h>
#include <math.h>
#include <stdint.h>

#define SEQ     2048
#define HIDDEN  2048
#define HD      128
#define NH      16
#define NKV     2

// ---------------- scratch (device globals) ----------------
__device__ __align__(16) __half g_qh [(size_t)NH  * SEQ * HD];
__device__ __align__(16) __half g_kh [(size_t)NKV * SEQ * HD];
__device__ __align__(16) __half g_vth[(size_t)NKV * HD * SEQ];
__device__ __align__(16) __half g_ah [(size_t)NH  * SEQ * HD];
__device__ __align__(16) float2 g_tab[(size_t)SEQ * 64];
#define QW_OFF 0
#define KW_OFF 4194304
#define VW_OFF 4718592
#define OW_OFF 5242880
#define W_TOT  9437184
__device__ __align__(16) __half g_wh[W_TOT];

// ================= helpers =================
__device__ __forceinline__ uint32_t smem_u32(const void* p) {
    uint32_t a;
    asm("{ .reg .u64 t; cvta.to.shared.u64 t, %1; cvt.u32.u64 %0, t; }" : "=r"(a) : "l"(p));
    return a;
}

#define LDSM4(r0, r1, r2, r3, addr) \
    asm volatile("ldmatrix.sync.aligned.m8n8.x4.shared.b16 {%0,%1,%2,%3}, [%4];" \
                 : "=r"(r0), "=r"(r1), "=r"(r2), "=r"(r3) : "r"(addr))

#define MMA16816(c, a, b) \
    asm volatile("mma.sync.aligned.m16n8k16.row.col.f32.f16.f16.f32 " \
                 "{%0,%1,%2,%3}, {%4,%5,%6,%7}, {%8,%9}, {%0,%1,%2,%3};" \
                 : "+f"((c)[0]), "+f"((c)[1]), "+f"((c)[2]), "+f"((c)[3]) \
                 : "r"((a)[0]), "r"((a)[1]), "r"((a)[2]), "r"((a)[3]), \
                   "r"((b)[0]), "r"((b)[1]))

#define CPA16(dst, src) \
    asm volatile("cp.async.cg.shared.global [%0], [%1], 16;" :: "r"(dst), "l"(src))
#define CPA_COMMIT()  asm volatile("cp.async.commit_group;")
#define CPA_WAIT0()   asm volatile("cp.async.wait_group 0;")
#define CPA_WAIT1()   asm volatile("cp.async.wait_group 1;")

// ================= fused Q/K/V projection: M-tile 64, K-chunk 32, A-prefetch depth 2 =================
// per-buffer smem: AH [0,5120), BH [5120,15360); double buffered
#define ROWB   80
#define ATILE  5120
#define PBUF   15360
#define PSMB   (2 * PBUF)

__device__ __forceinline__ void cvt_hi8(const float* __restrict__ xs,
                                        uint32_t* __restrict__ hw)
{
#pragma unroll
    for (int q = 0; q < 4; q++) {
        __half2 h = __floats2half2_rn(xs[2 * q], xs[2 * q + 1]);
        hw[q] = *reinterpret_cast<uint32_t*>(&h);
    }
}

// z<NH: Q head -> rope -> g_qh; z<NH+NKV: K -> rope -> g_kh; else V -> transpose -> g_vth.
__global__ __launch_bounds__(256, 2)
void proj_k(const float* __restrict__ qhid, const float* __restrict__ khid,
            const float* __restrict__ vhid, const __half* __restrict__ wh,
            const float2* __restrict__ tab)
{
    extern __shared__ char dsm[];
    const int tid  = threadIdx.x;
    const int wid  = tid >> 5;
    const int lane = tid & 31;
    const int wm   = (wid >> 2) << 5;
    const int wn16 = (wid & 3) << 4;
    const int zorig = blockIdx.z;
    const int m0   = blockIdx.y << 6;

    const float*  A;
    const __half* B;
    if (zorig < NH)            { A = qhid + (long)zorig * SEQ * HIDDEN; B = wh + QW_OFF; }
    else if (zorig < NH + NKV) { A = khid + (long)(zorig - NH) * SEQ * HIDDEN; B = wh + KW_OFF + (long)(zorig - NH) * HD * HIDDEN; }
    else                       { A = vhid + (long)(zorig - NH - NKV) * SEQ * HIDDEN; B = wh + VW_OFF + (long)(zorig - NH - NKV) * HD * HIDDEN; }
    if (zorig < NH) B += (long)zorig * HD * HIDDEN;
    A += (long)m0 * HIDDEN;

    float acc[2][4][4];
#pragma unroll
    for (int i = 0; i < 2; i++)
#pragma unroll
        for (int j = 0; j < 4; j++)
#pragma unroll
            for (int q = 0; q < 4; q++) acc[i][j][q] = 0.f;

    const uint32_t smbase = smem_u32(dsm);
    const int a_row  = wm + (lane & 15);
    const int a_koff = (lane >> 4) << 4;
    const int brow   = (lane & 7) + ((lane >> 4) & 1) * 8;
    const int b_koff = ((lane >> 3) & 1) << 4;

    const int arow = tid >> 2, aunit = tid & 3;
    const int asoff = arow * ROWB + aunit * 16;
    const int br_   = tid >> 1, bhalf = tid & 1;
    const uint32_t bcp_off = ATILE + (uint32_t)br_ * ROWB + (uint32_t)bhalf * 32;
    const long     bcp_src = (long)br_ * HIDDEN + bhalf * 16;

    float ra[2][8];
    // ---- prologue: chunk 0 into smem, chunk 1 into registers ----
    {
        CPA16(smbase + bcp_off,      B + bcp_src);
        CPA16(smbase + bcp_off + 16, B + bcp_src + 8);
        const float4* pa = (const float4*)(A + (long)arow * HIDDEN + aunit * 8);
        *(float4*)(ra[0])     = __ldcs(pa);
        *(float4*)(ra[0] + 4) = __ldcs(pa + 1);
        uint32_t hw[4];
        cvt_hi8(ra[0], hw);
        *(uint4*)(dsm + asoff) = make_uint4(hw[0], hw[1], hw[2], hw[3]);
        const float4* pa1 = (const float4*)(A + (long)arow * HIDDEN + 32 + aunit * 8);
        *(float4*)(ra[1])     = __ldcs(pa1);
        *(float4*)(ra[1] + 4) = __ldcs(pa1 + 1);
        CPA_COMMIT();
        CPA_WAIT0();
    }
    __syncthreads();

#pragma unroll 2
    for (int i = 0; i < 64; i++) {
        // B (depth 1) + A (depth 2) prefetch
        if (i + 1 < 64) {
            const int k0 = (i + 1) << 5;
            const uint32_t bb = smbase + ((i + 1) & 1) * PBUF;
            CPA16(bb + bcp_off,      B + k0 + bcp_src);
            CPA16(bb + bcp_off + 16, B + k0 + bcp_src + 8);
            CPA_COMMIT();
        }
        if (i + 2 < 64) {
            const int k2 = (i + 2) << 5;
            const float4* pa = (const float4*)(A + (long)arow * HIDDEN + k2 + aunit * 8);
            *(float4*)(ra[i & 1])     = __ldcs(pa);
            *(float4*)(ra[i & 1] + 4) = __ldcs(pa + 1);
        }
        // MMA on current buffer
        const uint32_t tb = smbase + (i & 1) * PBUF;
#pragma unroll
        for (int ks = 0; ks < 2; ks++) {
            uint32_t bh[4][2];
            const uint32_t ka = ks * 32 + a_koff;
            const uint32_t kb = ks * 32 + b_koff;
#pragma unroll
            for (int p = 0; p < 2; p++) {
                uint32_t r0, r1, r2, r3;
                LDSM4(r0, r1, r2, r3,
                      tb + ATILE + (uint32_t)(wn16 + p * 64 + brow) * ROWB + kb);
                bh[2 * p][0] = r0; bh[2 * p][1] = r1;
                bh[2 * p + 1][0] = r2; bh[2 * p + 1][1] = r3;
            }
#pragma unroll
            for (int mi = 0; mi < 2; mi++) {
                uint32_t ah[4];
                LDSM4(ah[0], ah[1], ah[2], ah[3],
                      tb + (uint32_t)(a_row + mi * 16) * ROWB + ka);
#pragma unroll
                for (int ni = 0; ni < 4; ni++) MMA16816(acc[mi][ni], ah, bh[ni]);
            }
        }
        // store chunk i+1's A (already in registers) into the other buffer
        if (i + 1 < 64) {
            char* buf = dsm + ((i + 1) & 1) * PBUF;
            uint32_t hw[4];
            cvt_hi8(ra[(i + 1) & 1], hw);
            *(uint4*)(buf + asoff) = make_uint4(hw[0], hw[1], hw[2], hw[3]);
            CPA_WAIT0();
        }
        __syncthreads();
    }

    // ---------------- epilogue ----------------
    const int g = lane >> 2, t = lane & 3;

    if (zorig < NH + NKV) {
        __half* dst = (zorig < NH)
            ? (g_qh + (long)zorig * SEQ * HD)
            : (g_kh + (long)(zorig - NH) * SEQ * HD);
#pragma unroll
        for (int mi = 0; mi < 2; mi++) {
            const int l0 = m0 + wm + mi * 16 + g;
#pragma unroll
            for (int pr = 0; pr < 2; pr++) {
                const int i0 = wn16 + pr * 8 + t * 2;
#pragma unroll
                for (int rr = 0; rr < 2; rr++) {
                    const int l = l0 + rr * 8;
                    const int e = rr * 2;
                    const float2 cs0 = tab[l * 64 + i0];
                    const float2 cs1 = tab[l * 64 + i0 + 1];
                    const float x1a = acc[mi][pr][e],     x1b = acc[mi][pr][e + 1];
                    const float x2a = acc[mi][pr + 2][e], x2b = acc[mi][pr + 2][e + 1];
                    *(__half2*)(dst + (long)l * HD + i0) =
                        __floats2half2_rn(x1a * cs0.x - x2a * cs0.y,
                                          x1b * cs1.x - x2b * cs1.y);
                    *(__half2*)(dst + (long)l * HD + i0 + 64) =
                        __floats2half2_rn(x2a * cs0.x + x1a * cs0.y,
                                          x2b * cs1.x + x1b * cs1.y);
                }
            }
        }
    } else {
        __half* sm = (__half*)dsm;
#pragma unroll
        for (int mi = 0; mi < 2; mi++) {
            const int r0 = wm + mi * 16 + g;
#pragma unroll
            for (int ni = 0; ni < 4; ni++) {
                const int cc = wn16 + (ni >> 1) * 64 + (ni & 1) * 8 + t * 2;
                sm[cc * 72 + r0]           = __float2half_rn(acc[mi][ni][0]);
                sm[(cc + 1) * 72 + r0]     = __float2half_rn(acc[mi][ni][1]);
                sm[cc * 72 + r0 + 8]       = __float2half_rn(acc[mi][ni][2]);
                sm[(cc + 1) * 72 + r0 + 8] = __float2half_rn(acc[mi][ni][3]);
            }
        }
        __syncthreads();
        __half* dst = g_vth + (long)(zorig - NH - NKV) * HD * SEQ;
        const int col = tid >> 1, rh = (tid & 1) << 5;
        const __half* src = sm + col * 72 + rh;
        __half* gp = dst + (long)col * SEQ + m0 + rh;
#pragma unroll
        for (int q = 0; q < 4; q++)
            *(uint4*)(gp + q * 8) = *(const uint4*)(src + q * 8);
    }
}

// ================= O projection: one-shot K=128 (R10 validated epilogue) =================
#define OROW  272
#define OASZ  34816
#define OSMB  69632

__global__ __launch_bounds__(256, 2)
void oproj_k(const __half* __restrict__ ahh, const __half* __restrict__ whO,
             float* __restrict__ out)
{
    extern __shared__ char dsm[];
    const int tid  = threadIdx.x;
    const int wid  = tid >> 5;
    const int lane = tid & 31;
    const int wm   = (wid >> 2) << 6;
    const int wn   = (wid & 3) << 5;
    const int z    = blockIdx.z;
    const int m0   = blockIdx.y << 7;
    const int n0   = blockIdx.x << 7;

    const __half* A = ahh + ((long)z * SEQ + m0) * HD;
    const __half* B = whO + (long)n0 * HIDDEN + (long)z * HD;
    float*        C = out + (long)z * SEQ * HIDDEN;

    const uint32_t smbase = smem_u32(dsm);

#pragma unroll
    for (int i = 0; i < 8; i++) {
        const int u = tid + (i << 8);
        const int row = u >> 4, un = u & 15;
        CPA16(smbase + row * OROW + un * 16, A + (long)row * HD + un * 8);
        CPA16(smbase + OASZ + row * OROW + un * 16, B + (long)row * HIDDEN + un * 8);
    }
    CPA_COMMIT();
    CPA_WAIT0();
    __syncthreads();

    float acc[4][4][4];
#pragma unroll
    for (int i = 0; i < 4; i++)
#pragma unroll
        for (int j = 0; j < 4; j++)
#pragma unroll
            for (int q = 0; q < 4; q++) acc[i][j][q] = 0.f;

    const int a_row  = wm + (lane & 15);
    const int a_koff = (lane >> 4) << 4;
    const int brow   = (lane & 7) + ((lane >> 4) & 1) * 8;
    const int b_koff = ((lane >> 3) & 1) << 4;

#pragma unroll
    for (int ks = 0; ks < 8; ks++) {
        uint32_t bh[4][2];
        const uint32_t ka = ks * 32 + a_koff;
        const uint32_t kb = ks * 32 + b_koff;
#pragma unroll
        for (int p = 0; p < 2; p++) {
            uint32_t r0, r1, r2, r3;
            LDSM4(r0, r1, r2, r3,
                  smbase + OASZ + (uint32_t)(wn + p * 16 + brow) * OROW + kb);
            bh[2 * p][0] = r0; bh[2 * p][1] = r1;
            bh[2 * p + 1][0] = r2; bh[2 * p + 1][1] = r3;
        }
#pragma unroll
        for (int mi = 0; mi < 4; mi++) {
            uint32_t ah[4];
            LDSM4(ah[0], ah[1], ah[2], ah[3],
                  smbase + (uint32_t)(a_row + mi * 16) * OROW + ka);
#pragma unroll
            for (int ni = 0; ni < 4; ni++) MMA16816(acc[mi][ni], ah, bh[ni]);
        }
    }

    const int g = lane >> 2, t = lane & 3;
#pragma unroll
    for (int mi = 0; mi < 4; mi++) {
        const int r0 = m0 + wm + mi * 16 + g;
#pragma unroll
        for (int ni = 0; ni < 4; ni++) {
            const int cc = n0 + wn + ni * 8 + t * 2;
            __stcs((float2*)(C + (long)r0 * HIDDEN + cc),
                   make_float2(acc[mi][ni][0], acc[mi][ni][1]));
            __stcs((float2*)(C + (long)(r0 + 8) * HIDDEN + cc),
                   make_float2(acc[mi][ni][2], acc[mi][ni][3]));
        }
    }
}

// ================= flash attention (unchanged, validated) =================
#define K_OFF  17408
#define KBUFB  17408
#define V_OFF  52224
#define VBUFB  18432
#define FSMEM  89088
#define FC     0.12751744f

__device__ __forceinline__ void kv_prefetch(uint32_t smb, int buf, int kv0,
    const __half* __restrict__ khp, const __half* __restrict__ vhp, int tid)
{
#pragma unroll
    for (int i = 0; i < 8; i++) {
        int t = tid + (i << 7);
        int unit = t & 15, row = t >> 4;
        CPA16(smb + K_OFF + buf * KBUFB + row * 272 + unit * 16,
              khp + (long)(kv0 + row) * HD + unit * 8);
    }
#pragma unroll
    for (int i = 0; i < 8; i++) {
        int t = tid + (i << 7);
        int unit = t & 7, row = t >> 3;
        CPA16(smb + V_OFF + buf * VBUFB + row * 144 + unit * 16,
              vhp + (long)row * SEQ + kv0 + unit * 8);
    }
}

__global__ __launch_bounds__(128, 2)
void flash_k(const __half* __restrict__ qhg, const __half* __restrict__ khg,
             const __half* __restrict__ vhg, __half* __restrict__ oah)
{
    extern __shared__ char dsm[];
    const uint32_t smb = smem_u32(dsm);
    const int tid  = threadIdx.x;
    const int w    = tid >> 5;
    const int lane = tid & 31;
    const int z    = blockIdx.x;
    const int mb   = 31 - blockIdx.y;
    const int kvh  = z >> 3;
    const int m0   = mb << 6;
    const int nt   = mb + 1;

    const __half* qhp = qhg + ((long)z * SEQ + m0) * HD;
    const __half* khp = khg + (long)kvh * SEQ * HD;
    const __half* vhp = vhg + (long)kvh * HD * SEQ;

#pragma unroll
    for (int i = 0; i < 8; i++) {
        int t = tid + (i << 7);
        int unit = t & 15, row = t >> 4;
        CPA16(smb + row * 272 + unit * 16, qhp + (long)row * HD + unit * 8);
    }
    CPA_COMMIT();
    kv_prefetch(smb, 0, 0, khp, vhp, tid);
    CPA_COMMIT();

    CPA_WAIT1();
    __syncthreads();
    const uint32_t qa_h = smb + (uint32_t)((w << 4) + (lane & 15)) * 272 + ((lane >> 4) << 4);
    uint32_t qf[8][4];
#pragma unroll
    for (int j = 0; j < 8; j++)
        LDSM4(qf[j][0], qf[j][1], qf[j][2], qf[j][3], qa_h + j * 32);

    float o[16][4];
#pragma unroll
    for (int nb = 0; nb < 16; nb++)
#pragma unroll
        for (int q = 0; q < 4; q++) o[nb][q] = 0.f;
    float mr0 = -1e30f, mr1 = -1e30f, l0 = 0.f, l1 = 0.f;

    const int wrow = m0 + (w << 4);
    const uint32_t brow = (lane & 7) + ((lane >> 4) & 1) * 8;
    const uint32_t bko  = ((lane >> 3) & 1) << 4;

    int buf = 0;
    for (int it = 0; it < nt; it++) {
        if (it + 1 < nt) {
            kv_prefetch(smb, buf ^ 1, (it + 1) << 6, khp, vhp, tid);
            CPA_COMMIT();
            CPA_WAIT1();
        } else {
            CPA_WAIT0();
        }
        __syncthreads();

        const int kv0 = it << 6;
        {
            const uint32_t kb_h = smb + K_OFF + buf * KBUFB;
            const uint32_t vb_h = smb + V_OFF + buf * VBUFB;

            float s[8][4];
#pragma unroll
            for (int nb = 0; nb < 8; nb++)
#pragma unroll
                for (int q = 0; q < 4; q++) s[nb][q] = 0.f;

#pragma unroll
            for (int j = 0; j < 8; j++) {
#pragma unroll
                for (int g16 = 0; g16 < 4; g16++) {
                    uint32_t bh[4];
                    const uint32_t ba = (uint32_t)(g16 * 16 + brow) * 272 + bko + j * 32;
                    LDSM4(bh[0], bh[1], bh[2], bh[3], kb_h + ba);
                    MMA16816(s[2 * g16],     qf[j], bh);
                    MMA16816(s[2 * g16 + 1], qf[j], bh + 2);
                }
            }

            const int r0 = wrow + (lane >> 2);
            const int c0 = kv0 + ((lane & 3) << 1);
            if (kv0 + 63 > wrow) {
#pragma unroll
                for (int nb = 0; nb < 8; nb++) {
                    const int c = c0 + nb * 8;
                    if (c     > r0    ) s[nb][0] = -1e30f;
                    if (c + 1 > r0    ) s[nb][1] = -1e30f;
                    if (c     > r0 + 8) s[nb][2] = -1e30f;
                    if (c + 1 > r0 + 8) s[nb][3] = -1e30f;
                }
            }

            float tm0 = -1e30f, tm1 = -1e30f;
#pragma unroll
            for (int nb = 0; nb < 8; nb++) {
                tm0 = fmaxf(tm0, fmaxf(s[nb][0], s[nb][1]));
                tm1 = fmaxf(tm1, fmaxf(s[nb][2], s[nb][3]));
            }
            tm0 = fmaxf(tm0, __shfl_xor_sync(0xffffffffu, tm0, 1));
            tm0 = fmaxf(tm0, __shfl_xor_sync(0xffffffffu, tm0, 2));
            tm1 = fmaxf(tm1, __shfl_xor_sync(0xffffffffu, tm1, 1));
            tm1 = fmaxf(tm1, __shfl_xor_sync(0xffffffffu, tm1, 2));
            const float mn0 = fmaxf(mr0, tm0), mn1 = fmaxf(mr1, tm1);
            const float sf0 = exp2f((mr0 - mn0) * FC);
            const float sf1 = exp2f((mr1 - mn1) * FC);
            mr0 = mn0; mr1 = mn1;
            l0 *= sf0;  l1 *= sf1;
#pragma unroll
            for (int nb = 0; nb < 16; nb++) {
                o[nb][0] *= sf0; o[nb][1] *= sf0;
                o[nb][2] *= sf1; o[nb][3] *= sf1;
            }
            float rs0 = 0.f, rs1 = 0.f;
#pragma unroll
            for (int nb = 0; nb < 8; nb++) {
                s[nb][0] = exp2f((s[nb][0] - mn0) * FC); rs0 += s[nb][0];
                s[nb][1] = exp2f((s[nb][1] - mn0) * FC); rs0 += s[nb][1];
                s[nb][2] = exp2f((s[nb][2] - mn1) * FC); rs1 += s[nb][2];
                s[nb][3] = exp2f((s[nb][3] - mn1) * FC); rs1 += s[nb][3];
            }
            rs0 += __shfl_xor_sync(0xffffffffu, rs0, 1);
            rs0 += __shfl_xor_sync(0xffffffffu, rs0, 2);
            rs1 += __shfl_xor_sync(0xffffffffu, rs1, 1);
            rs1 += __shfl_xor_sync(0xffffffffu, rs1, 2);
            l0 += rs0; l1 += rs1;

#pragma unroll
            for (int j = 0; j < 4; j++) {
                uint32_t pha[4];
#pragma unroll
                for (int hq = 0; hq < 4; hq++) {
                    const int nb = 2 * j + (hq >> 1);
                    const int e  = (hq & 1) << 1;
                    __half2 h = __floats2half2_rn(s[nb][e], s[nb][e + 1]);
                    pha[hq] = *reinterpret_cast<uint32_t*>(&h);
                }
#pragma unroll
                for (int g16 = 0; g16 < 8; g16++) {
                    uint32_t bh[4];
                    const uint32_t ba = (uint32_t)(g16 * 16 + brow) * 144 + bko + j * 32;
                    LDSM4(bh[0], bh[1], bh[2], bh[3], vb_h + ba);
                    MMA16816(o[2 * g16],     pha, bh);
                    MMA16816(o[2 * g16 + 1], pha, bh + 2);
                }
            }
        }
        __syncthreads();
        buf ^= 1;
    }

    const float inv0 = 1.f / l0, inv1 = 1.f / l1;
    const int r0 = wrow + (lane >> 2);
    const long base0 = ((long)z * SEQ + r0) * HD + ((lane & 3) << 1);
    const long base1 = base0 + 8 * HD;
#pragma unroll
    for (int nb = 0; nb < 16; nb++) {
        *(__half2*)(oah + base0 + nb * 8) =
            __floats2half2_rn(o[nb][0] * inv0, o[nb][1] * inv0);
        *(__half2*)(oah + base1 + nb * 8) =
            __floats2half2_rn(o[nb][2] * inv1, o[nb][3] * inv1);
    }
}

// ---------------- prep: rope table + weight cvt in one launch ----------------
#define TAB_BLKS 512
__global__ __launch_bounds__(256)
void prep_k(const int* __restrict__ pos, float2* __restrict__ tab,
            const float* __restrict__ qw, const float* __restrict__ kw,
            const float* __restrict__ vw, const float* __restrict__ ow,
            __half* __restrict__ d)
{
    const int bid = blockIdx.x;
    if (bid < TAB_BLKS) {
        int idx = bid * 256 + threadIdx.x;
        if (idx >= SEQ * 64) return;
        int i = idx & 63;
        int l = idx >> 6;
        float invf = exp2f(-(float)i * 0.31143075889569023f);
        float ang  = (float)pos[l] * invf;
        float q  = rintf(ang * 0.15915494309189535f);
        float r  = ang - q * 6.28125f;
        r        = r   - q * 1.9353071795864769e-3f;
        float s, c;
        sincosf(r, &s, &c);
        tab[idx] = make_float2(c, s);
        return;
    }
    int e = ((bid - TAB_BLKS) * 256 + threadIdx.x) << 2;
    if (e >= W_TOT) return;
    const float* s;
    if      (e < KW_OFF) s = qw + e;
    else if (e < VW_OFF) s = kw + (e - KW_OFF);
    else if (e < OW_OFF) s = vw + (e - VW_OFF);
    else                 s = ow + (e - OW_OFF);
    float4 v = *(const float4*)s;
    ((__half2*)(d + e))[0] = __floats2half2_rn(v.x, v.y);
    ((__half2*)(d + e))[1] = __floats2half2_rn(v.z, v.w);
}

// ---------------- launch ----------------
extern "C" void kernel_launch(void* const* d_in, const int* in_sizes, int n_in,
                              void* d_out, int out_size)
{
    const float* qhid = (const float*)d_in[0];
    const float* khid = (const float*)d_in[1];
    const float* vhid = (const float*)d_in[2];
    const int*   pos  = (const int*)  d_in[4];
    const float* qw   = (const float*)d_in[5];
    const float* kw   = (const float*)d_in[6];
    const float* vw   = (const float*)d_in[7];
    const float* ow   = (const float*)d_in[8];
    float*       out  = (float*)d_out;

    __half *qhh, *khh, *vth, *ahh, *wh;
    float2* tab;
    cudaGetSymbolAddress((void**)&qhh, g_qh);
    cudaGetSymbolAddress((void**)&khh, g_kh);
    cudaGetSymbolAddress((void**)&vth, g_vth);
    cudaGetSymbolAddress((void**)&ahh, g_ah);
    cudaGetSymbolAddress((void**)&wh,  g_wh);
    cudaGetSymbolAddress((void**)&tab, g_tab);

    cudaFuncSetAttribute(proj_k,  cudaFuncAttributeMaxDynamicSharedMemorySize, PSMB);
    cudaFuncSetAttribute(oproj_k, cudaFuncAttributeMaxDynamicSharedMemorySize, OSMB);
    cudaFuncSetAttribute(flash_k, cudaFuncAttributeMaxDynamicSharedMemorySize, FSMEM);

    prep_k<<<TAB_BLKS + (W_TOT / 4 + 255) / 256, 256>>>(pos, tab, qw, kw, vw, ow, wh);
    proj_k<<<dim3(1, 32, NH + 2 * NKV), 256, PSMB>>>(qhid, khid, vhid, wh, tab);
    flash_k<<<dim3(NH, 32), 128, FSMEM>>>(qhh, khh, vth, ahh);
    oproj_k<<<dim3(16, 16, NH), 256, OSMB>>>(ahh, wh + OW_OFF, out);
}

// round 14
// speedup vs baseline: 1.2008x; 1.0610x over previous
#include <cuda_runtime.h>
#include <cuda_fp16.h>
#include <math.h>
#include <stdint.h>

#define SEQ     2048
#define HIDDEN  2048
#define HD      128
#define NH      16
#define NKV     2

// ---------------- scratch (device globals) ----------------
__device__ __align__(16) __half g_qh [(size_t)NH  * SEQ * HD];
__device__ __align__(16) __half g_kh [(size_t)NKV * SEQ * HD];
__device__ __align__(16) __half g_vth[(size_t)NKV * HD * SEQ];
__device__ __align__(16) __half g_ah [(size_t)NH  * SEQ * HD];
__device__ __align__(16) float2 g_tab[(size_t)SEQ * 64];
#define QW_OFF 0
#define KW_OFF 4194304
#define VW_OFF 4718592
#define OW_OFF 5242880
#define W_TOT  9437184
__device__ __align__(16) __half g_wh[W_TOT];

// ================= helpers =================
__device__ __forceinline__ uint32_t smem_u32(const void* p) {
    uint32_t a;
    asm("{ .reg .u64 t; cvta.to.shared.u64 t, %1; cvt.u32.u64 %0, t; }" : "=r"(a) : "l"(p));
    return a;
}

#define LDSM4(r0, r1, r2, r3, addr) \
    asm volatile("ldmatrix.sync.aligned.m8n8.x4.shared.b16 {%0,%1,%2,%3}, [%4];" \
                 : "=r"(r0), "=r"(r1), "=r"(r2), "=r"(r3) : "r"(addr))

#define MMA16816(c, a, b) \
    asm volatile("mma.sync.aligned.m16n8k16.row.col.f32.f16.f16.f32 " \
                 "{%0,%1,%2,%3}, {%4,%5,%6,%7}, {%8,%9}, {%0,%1,%2,%3};" \
                 : "+f"((c)[0]), "+f"((c)[1]), "+f"((c)[2]), "+f"((c)[3]) \
                 : "r"((a)[0]), "r"((a)[1]), "r"((a)[2]), "r"((a)[3]), \
                   "r"((b)[0]), "r"((b)[1]))

#define CPA16(dst, src) \
    asm volatile("cp.async.cg.shared.global [%0], [%1], 16;" :: "r"(dst), "l"(src))
#define CPA_COMMIT()  asm volatile("cp.async.commit_group;")
#define CPA_WAIT0()   asm volatile("cp.async.wait_group 0;")
#define CPA_WAIT1()   asm volatile("cp.async.wait_group 1;")

// ================= fused Q/K/V projection =================
// M-tile 64, K-chunk 32; A double-buffered (regs depth 2), B TRIPLE-buffered smem.
// smem: A0 [0,5120) A1 [5120,10240) B0 [10240,20480) B1 [20480,30720) B2 [30720,40960)
#define ROWB   80
#define ATILE  5120
#define PB_OFF 10240
#define PBSZ   10240
#define PSMB   40960

__device__ __forceinline__ void cvt_hi8(const float* __restrict__ xs,
                                        uint32_t* __restrict__ hw)
{
#pragma unroll
    for (int q = 0; q < 4; q++) {
        __half2 h = __floats2half2_rn(xs[2 * q], xs[2 * q + 1]);
        hw[q] = *reinterpret_cast<uint32_t*>(&h);
    }
}

// z<NH: Q -> rope -> g_qh; z<NH+NKV: K -> rope -> g_kh; else V -> transpose -> g_vth.
__global__ __launch_bounds__(256, 2)
void proj_k(const float* __restrict__ qhid, const float* __restrict__ khid,
            const float* __restrict__ vhid, const __half* __restrict__ wh,
            const float2* __restrict__ tab)
{
    extern __shared__ char dsm[];
    const int tid  = threadIdx.x;
    const int wid  = tid >> 5;
    const int lane = tid & 31;
    const int wm   = (wid >> 2) << 5;
    const int wn16 = (wid & 3) << 4;
    const int zorig = blockIdx.z;
    const int m0   = blockIdx.y << 6;

    const float*  A;
    const __half* B;
    if (zorig < NH)            { A = qhid + (long)zorig * SEQ * HIDDEN; B = wh + QW_OFF; }
    else if (zorig < NH + NKV) { A = khid + (long)(zorig - NH) * SEQ * HIDDEN; B = wh + KW_OFF + (long)(zorig - NH) * HD * HIDDEN; }
    else                       { A = vhid + (long)(zorig - NH - NKV) * SEQ * HIDDEN; B = wh + VW_OFF + (long)(zorig - NH - NKV) * HD * HIDDEN; }
    if (zorig < NH) B += (long)zorig * HD * HIDDEN;
    A += (long)m0 * HIDDEN;

    float acc[2][4][4];
#pragma unroll
    for (int i = 0; i < 2; i++)
#pragma unroll
        for (int j = 0; j < 4; j++)
#pragma unroll
            for (int q = 0; q < 4; q++) acc[i][j][q] = 0.f;

    const uint32_t smbase = smem_u32(dsm);
    const int a_row  = wm + (lane & 15);
    const int a_koff = (lane >> 4) << 4;
    const int brow   = (lane & 7) + ((lane >> 4) & 1) * 8;
    const int b_koff = ((lane >> 3) & 1) << 4;

    const int arow = tid >> 2, aunit = tid & 3;
    const int asoff = arow * ROWB + aunit * 16;
    const int br_   = tid >> 1, bhalf = tid & 1;
    const uint32_t bcp_off = (uint32_t)br_ * ROWB + (uint32_t)bhalf * 32;
    const long     bcp_src = (long)br_ * HIDDEN + bhalf * 16;

    float ra[2][8];
    // ---- prologue: B0, B1 in flight; A0 -> smem; A1 -> regs ----
    {
        CPA16(smbase + PB_OFF + bcp_off,      B + bcp_src);
        CPA16(smbase + PB_OFF + bcp_off + 16, B + bcp_src + 8);
        CPA_COMMIT();
        CPA16(smbase + PB_OFF + PBSZ + bcp_off,      B + 32 + bcp_src);
        CPA16(smbase + PB_OFF + PBSZ + bcp_off + 16, B + 32 + bcp_src + 8);
        CPA_COMMIT();
        const float4* pa = (const float4*)(A + (long)arow * HIDDEN + aunit * 8);
        *(float4*)(ra[0])     = __ldcs(pa);
        *(float4*)(ra[0] + 4) = __ldcs(pa + 1);
        uint32_t hw[4];
        cvt_hi8(ra[0], hw);
        *(uint4*)(dsm + asoff) = make_uint4(hw[0], hw[1], hw[2], hw[3]);
        const float4* pa1 = (const float4*)(A + (long)arow * HIDDEN + 32 + aunit * 8);
        *(float4*)(ra[1])     = __ldcs(pa1);
        *(float4*)(ra[1] + 4) = __ldcs(pa1 + 1);
        CPA_WAIT1();
    }
    __syncthreads();

    int bcur = 0;                      // B buffer index for current chunk (i % 3)
    for (int i = 0; i < 64; i++) {
        // prefetch chunk i+2: B into buf (i+2)%3, A into regs
        if (i + 2 < 64) {
            const int k2 = (i + 2) << 5;
            int b2 = bcur + 2; if (b2 >= 3) b2 -= 3;
            const uint32_t bb = smbase + PB_OFF + (uint32_t)b2 * PBSZ;
            CPA16(bb + bcp_off,      B + k2 + bcp_src);
            CPA16(bb + bcp_off + 16, B + k2 + bcp_src + 8);
            CPA_COMMIT();
            const float4* pa = (const float4*)(A + (long)arow * HIDDEN + k2 + aunit * 8);
            *(float4*)(ra[i & 1])     = __ldcs(pa);
            *(float4*)(ra[i & 1] + 4) = __ldcs(pa + 1);
        }
        // MMA: A buf (i&1), B buf bcur
        const uint32_t ta = smbase + (uint32_t)(i & 1) * ATILE;
        const uint32_t tbB = smbase + PB_OFF + (uint32_t)bcur * PBSZ;
#pragma unroll
        for (int ks = 0; ks < 2; ks++) {
            uint32_t bh[4][2];
            const uint32_t ka = ks * 32 + a_koff;
            const uint32_t kb = ks * 32 + b_koff;
#pragma unroll
            for (int p = 0; p < 2; p++) {
                uint32_t r0, r1, r2, r3;
                LDSM4(r0, r1, r2, r3,
                      tbB + (uint32_t)(wn16 + p * 64 + brow) * ROWB + kb);
                bh[2 * p][0] = r0; bh[2 * p][1] = r1;
                bh[2 * p + 1][0] = r2; bh[2 * p + 1][1] = r3;
            }
#pragma unroll
            for (int mi = 0; mi < 2; mi++) {
                uint32_t ah[4];
                LDSM4(ah[0], ah[1], ah[2], ah[3],
                      ta + (uint32_t)(a_row + mi * 16) * ROWB + ka);
#pragma unroll
                for (int ni = 0; ni < 4; ni++) MMA16816(acc[mi][ni], ah, bh[ni]);
            }
        }
        // store chunk i+1's A (in regs) into A buf (i+1)&1; drain B(i+1)
        if (i + 1 < 64) {
            char* buf = dsm + ((i + 1) & 1) * ATILE;
            uint32_t hw[4];
            cvt_hi8(ra[(i + 1) & 1], hw);
            *(uint4*)(buf + asoff) = make_uint4(hw[0], hw[1], hw[2], hw[3]);
            if (i + 2 < 64) CPA_WAIT1();   // 2 groups in flight: B(i+1) done
            else            CPA_WAIT0();   // tail: only B(i+1) in flight — drain it
        }
        __syncthreads();
        bcur = (bcur == 2) ? 0 : bcur + 1;
    }

    // ---------------- epilogue ----------------
    const int g = lane >> 2, t = lane & 3;

    if (zorig < NH + NKV) {
        __half* dst = (zorig < NH)
            ? (g_qh + (long)zorig * SEQ * HD)
            : (g_kh + (long)(zorig - NH) * SEQ * HD);
#pragma unroll
        for (int mi = 0; mi < 2; mi++) {
            const int l0 = m0 + wm + mi * 16 + g;
#pragma unroll
            for (int pr = 0; pr < 2; pr++) {
                const int i0 = wn16 + pr * 8 + t * 2;
#pragma unroll
                for (int rr = 0; rr < 2; rr++) {
                    const int l = l0 + rr * 8;
                    const int e = rr * 2;
                    const float2 cs0 = tab[l * 64 + i0];
                    const float2 cs1 = tab[l * 64 + i0 + 1];
                    const float x1a = acc[mi][pr][e],     x1b = acc[mi][pr][e + 1];
                    const float x2a = acc[mi][pr + 2][e], x2b = acc[mi][pr + 2][e + 1];
                    *(__half2*)(dst + (long)l * HD + i0) =
                        __floats2half2_rn(x1a * cs0.x - x2a * cs0.y,
                                          x1b * cs1.x - x2b * cs1.y);
                    *(__half2*)(dst + (long)l * HD + i0 + 64) =
                        __floats2half2_rn(x2a * cs0.x + x1a * cs0.y,
                                          x2b * cs1.x + x1b * cs1.y);
                }
            }
        }
    } else {
        __half* sm = (__half*)dsm;
#pragma unroll
        for (int mi = 0; mi < 2; mi++) {
            const int r0 = wm + mi * 16 + g;
#pragma unroll
            for (int ni = 0; ni < 4; ni++) {
                const int cc = wn16 + (ni >> 1) * 64 + (ni & 1) * 8 + t * 2;
                sm[cc * 72 + r0]           = __float2half_rn(acc[mi][ni][0]);
                sm[(cc + 1) * 72 + r0]     = __float2half_rn(acc[mi][ni][1]);
                sm[cc * 72 + r0 + 8]       = __float2half_rn(acc[mi][ni][2]);
                sm[(cc + 1) * 72 + r0 + 8] = __float2half_rn(acc[mi][ni][3]);
            }
        }
        __syncthreads();
        __half* dst = g_vth + (long)(zorig - NH - NKV) * HD * SEQ;
        const int col = tid >> 1, rh = (tid & 1) << 5;
        const __half* src = sm + col * 72 + rh;
        __half* gp = dst + (long)col * SEQ + m0 + rh;
#pragma unroll
        for (int q = 0; q < 4; q++)
            *(uint4*)(gp + q * 8) = *(const uint4*)(src + q * 8);
    }
}

// ================= O projection: 2 N-tiles per CTA, B double-loaded =================
// smem: A [0,34816), B1 [34816,69632), B2 [69632,104448)   (272B rows)
#define OROW  272
#define OASZ  34816
#define OSMB  104448

__global__ __launch_bounds__(256, 2)
void oproj_k(const __half* __restrict__ ahh, const __half* __restrict__ whO,
             float* __restrict__ out)
{
    extern __shared__ char dsm[];
    const int tid  = threadIdx.x;
    const int wid  = tid >> 5;
    const int lane = tid & 31;
    const int wm   = (wid >> 2) << 6;
    const int wn   = (wid & 3) << 5;
    const int z    = blockIdx.z;
    const int m0   = blockIdx.y << 7;
    const int n0   = blockIdx.x << 8;          // 2 x 128-wide n-tiles

    const __half* A  = ahh + ((long)z * SEQ + m0) * HD;
    const __half* B1 = whO + (long)n0 * HIDDEN + (long)z * HD;
    const __half* B2 = B1 + (long)128 * HIDDEN;
    float*        C  = out + (long)z * SEQ * HIDDEN;

    const uint32_t smbase = smem_u32(dsm);

    // group 1: A + B1
#pragma unroll
    for (int i = 0; i < 8; i++) {
        const int u = tid + (i << 8);
        const int row = u >> 4, un = u & 15;
        CPA16(smbase + row * OROW + un * 16, A + (long)row * HD + un * 8);
        CPA16(smbase + OASZ + row * OROW + un * 16, B1 + (long)row * HIDDEN + un * 8);
    }
    CPA_COMMIT();
    // group 2: B2 (covered by compute1 + store1)
#pragma unroll
    for (int i = 0; i < 8; i++) {
        const int u = tid + (i << 8);
        const int row = u >> 4, un = u & 15;
        CPA16(smbase + 2 * OASZ + row * OROW + un * 16, B2 + (long)row * HIDDEN + un * 8);
    }
    CPA_COMMIT();
    CPA_WAIT1();
    __syncthreads();

    const int a_row  = wm + (lane & 15);
    const int a_koff = (lane >> 4) << 4;
    const int brow   = (lane & 7) + ((lane >> 4) & 1) * 8;
    const int b_koff = ((lane >> 3) & 1) << 4;
    const int g = lane >> 2, t = lane & 3;

#pragma unroll
    for (int half = 0; half < 2; half++) {
        float acc[4][4][4];
#pragma unroll
        for (int i = 0; i < 4; i++)
#pragma unroll
            for (int j = 0; j < 4; j++)
#pragma unroll
                for (int q = 0; q < 4; q++) acc[i][j][q] = 0.f;

        const uint32_t bbase = smbase + (half ? 2 * OASZ : OASZ);
#pragma unroll
        for (int ks = 0; ks < 8; ks++) {
            uint32_t bh[4][2];
            const uint32_t ka = ks * 32 + a_koff;
            const uint32_t kb = ks * 32 + b_koff;
#pragma unroll
            for (int p = 0; p < 2; p++) {
                uint32_t r0, r1, r2, r3;
                LDSM4(r0, r1, r2, r3,
                      bbase + (uint32_t)(wn + p * 16 + brow) * OROW + kb);
                bh[2 * p][0] = r0; bh[2 * p][1] = r1;
                bh[2 * p + 1][0] = r2; bh[2 * p + 1][1] = r3;
            }
#pragma unroll
            for (int mi = 0; mi < 4; mi++) {
                uint32_t ah[4];
                LDSM4(ah[0], ah[1], ah[2], ah[3],
                      smbase + (uint32_t)(a_row + mi * 16) * OROW + ka);
#pragma unroll
                for (int ni = 0; ni < 4; ni++) MMA16816(acc[mi][ni], ah, bh[ni]);
            }
        }

        const int nb0 = n0 + half * 128;
#pragma unroll
        for (int mi = 0; mi < 4; mi++) {
            const int r0 = m0 + wm + mi * 16 + g;
#pragma unroll
            for (int ni = 0; ni < 4; ni++) {
                const int cc = nb0 + wn + ni * 8 + t * 2;
                __stcs((float2*)(C + (long)r0 * HIDDEN + cc),
                       make_float2(acc[mi][ni][0], acc[mi][ni][1]));
                __stcs((float2*)(C + (long)(r0 + 8) * HIDDEN + cc),
                       make_float2(acc[mi][ni][2], acc[mi][ni][3]));
            }
        }
        if (half == 0) {
            CPA_WAIT0();
            __syncthreads();
        }
    }
}

// ================= flash attention (unchanged, validated) =================
#define K_OFF  17408
#define KBUFB  17408
#define V_OFF  52224
#define VBUFB  18432
#define FSMEM  89088
#define FC     0.12751744f

__device__ __forceinline__ void kv_prefetch(uint32_t smb, int buf, int kv0,
    const __half* __restrict__ khp, const __half* __restrict__ vhp, int tid)
{
#pragma unroll
    for (int i = 0; i < 8; i++) {
        int t = tid + (i << 7);
        int unit = t & 15, row = t >> 4;
        CPA16(smb + K_OFF + buf * KBUFB + row * 272 + unit * 16,
              khp + (long)(kv0 + row) * HD + unit * 8);
    }
#pragma unroll
    for (int i = 0; i < 8; i++) {
        int t = tid + (i << 7);
        int unit = t & 7, row = t >> 3;
        CPA16(smb + V_OFF + buf * VBUFB + row * 144 + unit * 16,
              vhp + (long)row * SEQ + kv0 + unit * 8);
    }
}

__global__ __launch_bounds__(128, 2)
void flash_k(const __half* __restrict__ qhg, const __half* __restrict__ khg,
             const __half* __restrict__ vhg, __half* __restrict__ oah)
{
    extern __shared__ char dsm[];
    const uint32_t smb = smem_u32(dsm);
    const int tid  = threadIdx.x;
    const int w    = tid >> 5;
    const int lane = tid & 31;
    const int z    = blockIdx.x;
    const int mb   = 31 - blockIdx.y;
    const int kvh  = z >> 3;
    const int m0   = mb << 6;
    const int nt   = mb + 1;

    const __half* qhp = qhg + ((long)z * SEQ + m0) * HD;
    const __half* khp = khg + (long)kvh * SEQ * HD;
    const __half* vhp = vhg + (long)kvh * HD * SEQ;

#pragma unroll
    for (int i = 0; i < 8; i++) {
        int t = tid + (i << 7);
        int unit = t & 15, row = t >> 4;
        CPA16(smb + row * 272 + unit * 16, qhp + (long)row * HD + unit * 8);
    }
    CPA_COMMIT();
    kv_prefetch(smb, 0, 0, khp, vhp, tid);
    CPA_COMMIT();

    CPA_WAIT1();
    __syncthreads();
    const uint32_t qa_h = smb + (uint32_t)((w << 4) + (lane & 15)) * 272 + ((lane >> 4) << 4);
    uint32_t qf[8][4];
#pragma unroll
    for (int j = 0; j < 8; j++)
        LDSM4(qf[j][0], qf[j][1], qf[j][2], qf[j][3], qa_h + j * 32);

    float o[16][4];
#pragma unroll
    for (int nb = 0; nb < 16; nb++)
#pragma unroll
        for (int q = 0; q < 4; q++) o[nb][q] = 0.f;
    float mr0 = -1e30f, mr1 = -1e30f, l0 = 0.f, l1 = 0.f;

    const int wrow = m0 + (w << 4);
    const uint32_t brow = (lane & 7) + ((lane >> 4) & 1) * 8;
    const uint32_t bko  = ((lane >> 3) & 1) << 4;

    int buf = 0;
    for (int it = 0; it < nt; it++) {
        if (it + 1 < nt) {
            kv_prefetch(smb, buf ^ 1, (it + 1) << 6, khp, vhp, tid);
            CPA_COMMIT();
            CPA_WAIT1();
        } else {
            CPA_WAIT0();
        }
        __syncthreads();

        const int kv0 = it << 6;
        {
            const uint32_t kb_h = smb + K_OFF + buf * KBUFB;
            const uint32_t vb_h = smb + V_OFF + buf * VBUFB;

            float s[8][4];
#pragma unroll
            for (int nb = 0; nb < 8; nb++)
#pragma unroll
                for (int q = 0; q < 4; q++) s[nb][q] = 0.f;

#pragma unroll
            for (int j = 0; j < 8; j++) {
#pragma unroll
                for (int g16 = 0; g16 < 4; g16++) {
                    uint32_t bh[4];
                    const uint32_t ba = (uint32_t)(g16 * 16 + brow) * 272 + bko + j * 32;
                    LDSM4(bh[0], bh[1], bh[2], bh[3], kb_h + ba);
                    MMA16816(s[2 * g16],     qf[j], bh);
                    MMA16816(s[2 * g16 + 1], qf[j], bh + 2);
                }
            }

            const int r0 = wrow + (lane >> 2);
            const int c0 = kv0 + ((lane & 3) << 1);
            if (kv0 + 63 > wrow) {
#pragma unroll
                for (int nb = 0; nb < 8; nb++) {
                    const int c = c0 + nb * 8;
                    if (c     > r0    ) s[nb][0] = -1e30f;
                    if (c + 1 > r0    ) s[nb][1] = -1e30f;
                    if (c     > r0 + 8) s[nb][2] = -1e30f;
                    if (c + 1 > r0 + 8) s[nb][3] = -1e30f;
                }
            }

            float tm0 = -1e30f, tm1 = -1e30f;
#pragma unroll
            for (int nb = 0; nb < 8; nb++) {
                tm0 = fmaxf(tm0, fmaxf(s[nb][0], s[nb][1]));
                tm1 = fmaxf(tm1, fmaxf(s[nb][2], s[nb][3]));
            }
            tm0 = fmaxf(tm0, __shfl_xor_sync(0xffffffffu, tm0, 1));
            tm0 = fmaxf(tm0, __shfl_xor_sync(0xffffffffu, tm0, 2));
            tm1 = fmaxf(tm1, __shfl_xor_sync(0xffffffffu, tm1, 1));
            tm1 = fmaxf(tm1, __shfl_xor_sync(0xffffffffu, tm1, 2));
            const float mn0 = fmaxf(mr0, tm0), mn1 = fmaxf(mr1, tm1);
            const float sf0 = exp2f((mr0 - mn0) * FC);
            const float sf1 = exp2f((mr1 - mn1) * FC);
            mr0 = mn0; mr1 = mn1;
            l0 *= sf0;  l1 *= sf1;
#pragma unroll
            for (int nb = 0; nb < 16; nb++) {
                o[nb][0] *= sf0; o[nb][1] *= sf0;
                o[nb][2] *= sf1; o[nb][3] *= sf1;
            }
            float rs0 = 0.f, rs1 = 0.f;
#pragma unroll
            for (int nb = 0; nb < 8; nb++) {
                s[nb][0] = exp2f((s[nb][0] - mn0) * FC); rs0 += s[nb][0];
                s[nb][1] = exp2f((s[nb][1] - mn0) * FC); rs0 += s[nb][1];
                s[nb][2] = exp2f((s[nb][2] - mn1) * FC); rs1 += s[nb][2];
                s[nb][3] = exp2f((s[nb][3] - mn1) * FC); rs1 += s[nb][3];
            }
            rs0 += __shfl_xor_sync(0xffffffffu, rs0, 1);
            rs0 += __shfl_xor_sync(0xffffffffu, rs0, 2);
            rs1 += __shfl_xor_sync(0xffffffffu, rs1, 1);
            rs1 += __shfl_xor_sync(0xffffffffu, rs1, 2);
            l0 += rs0; l1 += rs1;

#pragma unroll
            for (int j = 0; j < 4; j++) {
                uint32_t pha[4];
#pragma unroll
                for (int hq = 0; hq < 4; hq++) {
                    const int nb = 2 * j + (hq >> 1);
                    const int e  = (hq & 1) << 1;
                    __half2 h = __floats2half2_rn(s[nb][e], s[nb][e + 1]);
                    pha[hq] = *reinterpret_cast<uint32_t*>(&h);
                }
#pragma unroll
                for (int g16 = 0; g16 < 8; g16++) {
                    uint32_t bh[4];
                    const uint32_t ba = (uint32_t)(g16 * 16 + brow) * 144 + bko + j * 32;
                    LDSM4(bh[0], bh[1], bh[2], bh[3], vb_h + ba);
                    MMA16816(o[2 * g16],     pha, bh);
                    MMA16816(o[2 * g16 + 1], pha, bh + 2);
                }
            }
        }
        __syncthreads();
        buf ^= 1;
    }

    const float inv0 = 1.f / l0, inv1 = 1.f / l1;
    const int r0 = wrow + (lane >> 2);
    const long base0 = ((long)z * SEQ + r0) * HD + ((lane & 3) << 1);
    const long base1 = base0 + 8 * HD;
#pragma unroll
    for (int nb = 0; nb < 16; nb++) {
        *(__half2*)(oah + base0 + nb * 8) =
            __floats2half2_rn(o[nb][0] * inv0, o[nb][1] * inv0);
        *(__half2*)(oah + base1 + nb * 8) =
            __floats2half2_rn(o[nb][2] * inv1, o[nb][3] * inv1);
    }
}

// ---------------- prep: rope table + weight cvt in one launch ----------------
#define TAB_BLKS 512
__global__ __launch_bounds__(256)
void prep_k(const int* __restrict__ pos, float2* __restrict__ tab,
            const float* __restrict__ qw, const float* __restrict__ kw,
            const float* __restrict__ vw, const float* __restrict__ ow,
            __half* __restrict__ d)
{
    const int bid = blockIdx.x;
    if (bid < TAB_BLKS) {
        int idx = bid * 256 + threadIdx.x;
        if (idx >= SEQ * 64) return;
        int i = idx & 63;
        int l = idx >> 6;
        float invf = exp2f(-(float)i * 0.31143075889569023f);
        float ang  = (float)pos[l] * invf;
        float q  = rintf(ang * 0.15915494309189535f);
        float r  = ang - q * 6.28125f;
        r        = r   - q * 1.9353071795864769e-3f;
        float s, c;
        sincosf(r, &s, &c);
        tab[idx] = make_float2(c, s);
        return;
    }
    int e = ((bid - TAB_BLKS) * 256 + threadIdx.x) << 2;
    if (e >= W_TOT) return;
    const float* s;
    if      (e < KW_OFF) s = qw + e;
    else if (e < VW_OFF) s = kw + (e - KW_OFF);
    else if (e < OW_OFF) s = vw + (e - VW_OFF);
    else                 s = ow + (e - OW_OFF);
    float4 v = *(const float4*)s;
    ((__half2*)(d + e))[0] = __floats2half2_rn(v.x, v.y);
    ((__half2*)(d + e))[1] = __floats2half2_rn(v.z, v.w);
}

// ---------------- launch ----------------
extern "C" void kernel_launch(void* const* d_in, const int* in_sizes, int n_in,
                              void* d_out, int out_size)
{
    const float* qhid = (const float*)d_in[0];
    const float* khid = (const float*)d_in[1];
    const float* vhid = (const float*)d_in[2];
    const int*   pos  = (const int*)  d_in[4];
    const float* qw   = (const float*)d_in[5];
    const float* kw   = (const float*)d_in[6];
    const float* vw   = (const float*)d_in[7];
    const float* ow   = (const float*)d_in[8];
    float*       out  = (float*)d_out;

    __half *qhh, *khh, *vth, *ahh, *wh;
    float2* tab;
    cudaGetSymbolAddress((void**)&qhh, g_qh);
    cudaGetSymbolAddress((void**)&khh, g_kh);
    cudaGetSymbolAddress((void**)&vth, g_vth);
    cudaGetSymbolAddress((void**)&ahh, g_ah);
    cudaGetSymbolAddress((void**)&wh,  g_wh);
    cudaGetSymbolAddress((void**)&tab, g_tab);

    cudaFuncSetAttribute(proj_k,  cudaFuncAttributeMaxDynamicSharedMemorySize, PSMB);
    cudaFuncSetAttribute(oproj_k, cudaFuncAttributeMaxDynamicSharedMemorySize, OSMB);
    cudaFuncSetAttribute(flash_k, cudaFuncAttributeMaxDynamicSharedMemorySize, FSMEM);

    prep_k<<<TAB_BLKS + (W_TOT / 4 + 255) / 256, 256>>>(pos, tab, qw, kw, vw, ow, wh);
    proj_k<<<dim3(1, 32, NH + 2 * NKV), 256, PSMB>>>(qhid, khid, vhid, wh, tab);
    flash_k<<<dim3(NH, 32), 128, FSMEM>>>(qhh, khh, vth, ahh);
    oproj_k<<<dim3(8, 16, NH), 256, OSMB>>>(ahh, wh + OW_OFF, out);
}

// round 15
// speedup vs baseline: 1.2047x; 1.0033x over previous
#include <cuda_runtime.h>
#include <cuda_fp16.h>
#include <math.h>
#include <stdint.h>

#define SEQ     2048
#define HIDDEN  2048
#define HD      128
#define NH      16
#define NKV     2

// ---------------- scratch (device globals) ----------------
__device__ __align__(16) __half g_qh [(size_t)NH  * SEQ * HD];
__device__ __align__(16) __half g_kh [(size_t)NKV * SEQ * HD];
__device__ __align__(16) __half g_vth[(size_t)NKV * HD * SEQ];
__device__ __align__(16) __half g_ah [(size_t)NH  * SEQ * HD];
__device__ __align__(16) float2 g_tab[(size_t)SEQ * 64];
#define QW_OFF 0
#define KW_OFF 4194304
#define VW_OFF 4718592
#define OW_OFF 5242880
#define W_TOT  9437184
__device__ __align__(16) __half g_wh[W_TOT];

// ================= helpers =================
__device__ __forceinline__ uint32_t smem_u32(const void* p) {
    uint32_t a;
    asm("{ .reg .u64 t; cvta.to.shared.u64 t, %1; cvt.u32.u64 %0, t; }" : "=r"(a) : "l"(p));
    return a;
}

#define LDSM4(r0, r1, r2, r3, addr) \
    asm volatile("ldmatrix.sync.aligned.m8n8.x4.shared.b16 {%0,%1,%2,%3}, [%4];" \
                 : "=r"(r0), "=r"(r1), "=r"(r2), "=r"(r3) : "r"(addr))

#define MMA16816(c, a, b) \
    asm volatile("mma.sync.aligned.m16n8k16.row.col.f32.f16.f16.f32 " \
                 "{%0,%1,%2,%3}, {%4,%5,%6,%7}, {%8,%9}, {%0,%1,%2,%3};" \
                 : "+f"((c)[0]), "+f"((c)[1]), "+f"((c)[2]), "+f"((c)[3]) \
                 : "r"((a)[0]), "r"((a)[1]), "r"((a)[2]), "r"((a)[3]), \
                   "r"((b)[0]), "r"((b)[1]))

#define CPA16(dst, src) \
    asm volatile("cp.async.cg.shared.global [%0], [%1], 16;" :: "r"(dst), "l"(src))
#define CPA_COMMIT()  asm volatile("cp.async.commit_group;")
#define CPA_WAIT0()   asm volatile("cp.async.wait_group 0;")
#define CPA_WAIT1()   asm volatile("cp.async.wait_group 1;")

// ================= fused Q/K/V projection (R14, validated) =================
// M-tile 64, K-chunk 32; A double-buffered (regs depth 2), B TRIPLE-buffered smem.
#define ROWB   80
#define ATILE  5120
#define PB_OFF 10240
#define PBSZ   10240
#define PSMB   40960

__device__ __forceinline__ void cvt_hi8(const float* __restrict__ xs,
                                        uint32_t* __restrict__ hw)
{
#pragma unroll
    for (int q = 0; q < 4; q++) {
        __half2 h = __floats2half2_rn(xs[2 * q], xs[2 * q + 1]);
        hw[q] = *reinterpret_cast<uint32_t*>(&h);
    }
}

__global__ __launch_bounds__(256, 2)
void proj_k(const float* __restrict__ qhid, const float* __restrict__ khid,
            const float* __restrict__ vhid, const __half* __restrict__ wh,
            const float2* __restrict__ tab)
{
    extern __shared__ char dsm[];
    const int tid  = threadIdx.x;
    const int wid  = tid >> 5;
    const int lane = tid & 31;
    const int wm   = (wid >> 2) << 5;
    const int wn16 = (wid & 3) << 4;
    const int zorig = blockIdx.z;
    const int m0   = blockIdx.y << 6;

    const float*  A;
    const __half* B;
    if (zorig < NH)            { A = qhid + (long)zorig * SEQ * HIDDEN; B = wh + QW_OFF; }
    else if (zorig < NH + NKV) { A = khid + (long)(zorig - NH) * SEQ * HIDDEN; B = wh + KW_OFF + (long)(zorig - NH) * HD * HIDDEN; }
    else                       { A = vhid + (long)(zorig - NH - NKV) * SEQ * HIDDEN; B = wh + VW_OFF + (long)(zorig - NH - NKV) * HD * HIDDEN; }
    if (zorig < NH) B += (long)zorig * HD * HIDDEN;
    A += (long)m0 * HIDDEN;

    float acc[2][4][4];
#pragma unroll
    for (int i = 0; i < 2; i++)
#pragma unroll
        for (int j = 0; j < 4; j++)
#pragma unroll
            for (int q = 0; q < 4; q++) acc[i][j][q] = 0.f;

    const uint32_t smbase = smem_u32(dsm);
    const int a_row  = wm + (lane & 15);
    const int a_koff = (lane >> 4) << 4;
    const int brow   = (lane & 7) + ((lane >> 4) & 1) * 8;
    const int b_koff = ((lane >> 3) & 1) << 4;

    const int arow = tid >> 2, aunit = tid & 3;
    const int asoff = arow * ROWB + aunit * 16;
    const int br_   = tid >> 1, bhalf = tid & 1;
    const uint32_t bcp_off = (uint32_t)br_ * ROWB + (uint32_t)bhalf * 32;
    const long     bcp_src = (long)br_ * HIDDEN + bhalf * 16;

    float ra[2][8];
    {
        CPA16(smbase + PB_OFF + bcp_off,      B + bcp_src);
        CPA16(smbase + PB_OFF + bcp_off + 16, B + bcp_src + 8);
        CPA_COMMIT();
        CPA16(smbase + PB_OFF + PBSZ + bcp_off,      B + 32 + bcp_src);
        CPA16(smbase + PB_OFF + PBSZ + bcp_off + 16, B + 32 + bcp_src + 8);
        CPA_COMMIT();
        const float4* pa = (const float4*)(A + (long)arow * HIDDEN + aunit * 8);
        *(float4*)(ra[0])     = __ldcs(pa);
        *(float4*)(ra[0] + 4) = __ldcs(pa + 1);
        uint32_t hw[4];
        cvt_hi8(ra[0], hw);
        *(uint4*)(dsm + asoff) = make_uint4(hw[0], hw[1], hw[2], hw[3]);
        const float4* pa1 = (const float4*)(A + (long)arow * HIDDEN + 32 + aunit * 8);
        *(float4*)(ra[1])     = __ldcs(pa1);
        *(float4*)(ra[1] + 4) = __ldcs(pa1 + 1);
        CPA_WAIT1();
    }
    __syncthreads();

    int bcur = 0;
    for (int i = 0; i < 64; i++) {
        if (i + 2 < 64) {
            const int k2 = (i + 2) << 5;
            int b2 = bcur + 2; if (b2 >= 3) b2 -= 3;
            const uint32_t bb = smbase + PB_OFF + (uint32_t)b2 * PBSZ;
            CPA16(bb + bcp_off,      B + k2 + bcp_src);
            CPA16(bb + bcp_off + 16, B + k2 + bcp_src + 8);
            CPA_COMMIT();
            const float4* pa = (const float4*)(A + (long)arow * HIDDEN + k2 + aunit * 8);
            *(float4*)(ra[i & 1])     = __ldcs(pa);
            *(float4*)(ra[i & 1] + 4) = __ldcs(pa + 1);
        }
        const uint32_t ta = smbase + (uint32_t)(i & 1) * ATILE;
        const uint32_t tbB = smbase + PB_OFF + (uint32_t)bcur * PBSZ;
#pragma unroll
        for (int ks = 0; ks < 2; ks++) {
            uint32_t bh[4][2];
            const uint32_t ka = ks * 32 + a_koff;
            const uint32_t kb = ks * 32 + b_koff;
#pragma unroll
            for (int p = 0; p < 2; p++) {
                uint32_t r0, r1, r2, r3;
                LDSM4(r0, r1, r2, r3,
                      tbB + (uint32_t)(wn16 + p * 64 + brow) * ROWB + kb);
                bh[2 * p][0] = r0; bh[2 * p][1] = r1;
                bh[2 * p + 1][0] = r2; bh[2 * p + 1][1] = r3;
            }
#pragma unroll
            for (int mi = 0; mi < 2; mi++) {
                uint32_t ah[4];
                LDSM4(ah[0], ah[1], ah[2], ah[3],
                      ta + (uint32_t)(a_row + mi * 16) * ROWB + ka);
#pragma unroll
                for (int ni = 0; ni < 4; ni++) MMA16816(acc[mi][ni], ah, bh[ni]);
            }
        }
        if (i + 1 < 64) {
            char* buf = dsm + ((i + 1) & 1) * ATILE;
            uint32_t hw[4];
            cvt_hi8(ra[(i + 1) & 1], hw);
            *(uint4*)(buf + asoff) = make_uint4(hw[0], hw[1], hw[2], hw[3]);
            if (i + 2 < 64) CPA_WAIT1();
            else            CPA_WAIT0();
        }
        __syncthreads();
        bcur = (bcur == 2) ? 0 : bcur + 1;
    }

    // epilogue
    const int g = lane >> 2, t = lane & 3;

    if (zorig < NH + NKV) {
        __half* dst = (zorig < NH)
            ? (g_qh + (long)zorig * SEQ * HD)
            : (g_kh + (long)(zorig - NH) * SEQ * HD);
#pragma unroll
        for (int mi = 0; mi < 2; mi++) {
            const int l0 = m0 + wm + mi * 16 + g;
#pragma unroll
            for (int pr = 0; pr < 2; pr++) {
                const int i0 = wn16 + pr * 8 + t * 2;
#pragma unroll
                for (int rr = 0; rr < 2; rr++) {
                    const int l = l0 + rr * 8;
                    const int e = rr * 2;
                    const float2 cs0 = tab[l * 64 + i0];
                    const float2 cs1 = tab[l * 64 + i0 + 1];
                    const float x1a = acc[mi][pr][e],     x1b = acc[mi][pr][e + 1];
                    const float x2a = acc[mi][pr + 2][e], x2b = acc[mi][pr + 2][e + 1];
                    *(__half2*)(dst + (long)l * HD + i0) =
                        __floats2half2_rn(x1a * cs0.x - x2a * cs0.y,
                                          x1b * cs1.x - x2b * cs1.y);
                    *(__half2*)(dst + (long)l * HD + i0 + 64) =
                        __floats2half2_rn(x2a * cs0.x + x1a * cs0.y,
                                          x2b * cs1.x + x1b * cs1.y);
                }
            }
        }
    } else {
        __half* sm = (__half*)dsm;
#pragma unroll
        for (int mi = 0; mi < 2; mi++) {
            const int r0 = wm + mi * 16 + g;
#pragma unroll
            for (int ni = 0; ni < 4; ni++) {
                const int cc = wn16 + (ni >> 1) * 64 + (ni & 1) * 8 + t * 2;
                sm[cc * 72 + r0]           = __float2half_rn(acc[mi][ni][0]);
                sm[(cc + 1) * 72 + r0]     = __float2half_rn(acc[mi][ni][1]);
                sm[cc * 72 + r0 + 8]       = __float2half_rn(acc[mi][ni][2]);
                sm[(cc + 1) * 72 + r0 + 8] = __float2half_rn(acc[mi][ni][3]);
            }
        }
        __syncthreads();
        __half* dst = g_vth + (long)(zorig - NH - NKV) * HD * SEQ;
        const int col = tid >> 1, rh = (tid & 1) << 5;
        const __half* src = sm + col * 72 + rh;
        __half* gp = dst + (long)col * SEQ + m0 + rh;
#pragma unroll
        for (int q = 0; q < 4; q++)
            *(uint4*)(gp + q * 8) = *(const uint4*)(src + q * 8);
    }
}

// ================= O projection: 4 N-tiles per CTA, rolling B pipeline =================
// smem: A [0,34816), Bbuf0 [34816,69632), Bbuf1 [69632,104448)
#define OROW  272
#define OASZ  34816
#define OSMB  104448

__global__ __launch_bounds__(256, 2)
void oproj_k(const __half* __restrict__ ahh, const __half* __restrict__ whO,
             float* __restrict__ out)
{
    extern __shared__ char dsm[];
    const int tid  = threadIdx.x;
    const int wid  = tid >> 5;
    const int lane = tid & 31;
    const int wm   = (wid >> 2) << 6;
    const int wn   = (wid & 3) << 5;
    const int z    = blockIdx.z;
    const int m0   = blockIdx.y << 7;
    const int n0   = blockIdx.x << 9;          // 4 x 128-wide n-tiles

    const __half* A  = ahh + ((long)z * SEQ + m0) * HD;
    float*        C  = out + (long)z * SEQ * HIDDEN;

    const uint32_t smbase = smem_u32(dsm);
    const int lrow = tid >> 4, lun = tid & 15;  // unused combined form below

    // ---- prologue: group0 = A + B(tile0) -> buf0 ; group1 = B(tile1) -> buf1 ----
    {
        const __half* B0 = whO + (long)n0 * HIDDEN + (long)z * HD;
#pragma unroll
        for (int i = 0; i < 8; i++) {
            const int u = tid + (i << 8);
            const int row = u >> 4, un = u & 15;
            CPA16(smbase + row * OROW + un * 16, A + (long)row * HD + un * 8);
            CPA16(smbase + OASZ + row * OROW + un * 16, B0 + (long)row * HIDDEN + un * 8);
        }
        CPA_COMMIT();
        const __half* B1 = B0 + (long)128 * HIDDEN;
#pragma unroll
        for (int i = 0; i < 8; i++) {
            const int u = tid + (i << 8);
            const int row = u >> 4, un = u & 15;
            CPA16(smbase + 2 * OASZ + row * OROW + un * 16, B1 + (long)row * HIDDEN + un * 8);
        }
        CPA_COMMIT();
        CPA_WAIT1();
    }
    __syncthreads();

    const int a_row  = wm + (lane & 15);
    const int a_koff = (lane >> 4) << 4;
    const int brow   = (lane & 7) + ((lane >> 4) & 1) * 8;
    const int b_koff = ((lane >> 3) & 1) << 4;
    const int g = lane >> 2, t4 = lane & 3;

#pragma unroll
    for (int t = 0; t < 4; t++) {
        float acc[4][4][4];
#pragma unroll
        for (int i = 0; i < 4; i++)
#pragma unroll
            for (int j = 0; j < 4; j++)
#pragma unroll
                for (int q = 0; q < 4; q++) acc[i][j][q] = 0.f;

        const uint32_t bbase = smbase + OASZ + (uint32_t)(t & 1) * OASZ;
#pragma unroll
        for (int ks = 0; ks < 8; ks++) {
            uint32_t bh[4][2];
            const uint32_t ka = ks * 32 + a_koff;
            const uint32_t kb = ks * 32 + b_koff;
#pragma unroll
            for (int p = 0; p < 2; p++) {
                uint32_t r0, r1, r2, r3;
                LDSM4(r0, r1, r2, r3,
                      bbase + (uint32_t)(wn + p * 16 + brow) * OROW + kb);
                bh[2 * p][0] = r0; bh[2 * p][1] = r1;
                bh[2 * p + 1][0] = r2; bh[2 * p + 1][1] = r3;
            }
#pragma unroll
            for (int mi = 0; mi < 4; mi++) {
                uint32_t ah[4];
                LDSM4(ah[0], ah[1], ah[2], ah[3],
                      smbase + (uint32_t)(a_row + mi * 16) * OROW + ka);
#pragma unroll
                for (int ni = 0; ni < 4; ni++) MMA16816(acc[mi][ni], ah, bh[ni]);
            }
        }

        // refill the buffer we just consumed with B(t+2), then store (covers fetch)
        if (t + 2 < 4) {
            __syncthreads();   // all warps finished reading buf (t&1)
            const __half* Bn = whO + (long)(n0 + (t + 2) * 128) * HIDDEN + (long)z * HD;
#pragma unroll
            for (int i = 0; i < 8; i++) {
                const int u = tid + (i << 8);
                const int row = u >> 4, un = u & 15;
                CPA16(bbase + row * OROW + un * 16, Bn + (long)row * HIDDEN + un * 8);
            }
            CPA_COMMIT();
        }

        const int nb0 = n0 + t * 128;
#pragma unroll
        for (int mi = 0; mi < 4; mi++) {
            const int r0 = m0 + wm + mi * 16 + g;
#pragma unroll
            for (int ni = 0; ni < 4; ni++) {
                const int cc = nb0 + wn + ni * 8 + t4 * 2;
                __stcs((float2*)(C + (long)r0 * HIDDEN + cc),
                       make_float2(acc[mi][ni][0], acc[mi][ni][1]));
                __stcs((float2*)(C + (long)(r0 + 8) * HIDDEN + cc),
                       make_float2(acc[mi][ni][2], acc[mi][ni][3]));
            }
        }

        if (t < 3) {
            if (t + 2 < 4) CPA_WAIT1();   // 2 groups in flight: B(t+1) done
            else           CPA_WAIT0();   // tail: drain B(t+1)
            __syncthreads();
        }
    }
}

// ================= flash attention (unchanged, validated) =================
#define K_OFF  17408
#define KBUFB  17408
#define V_OFF  52224
#define VBUFB  18432
#define FSMEM  89088
#define FC     0.12751744f

__device__ __forceinline__ void kv_prefetch(uint32_t smb, int buf, int kv0,
    const __half* __restrict__ khp, const __half* __restrict__ vhp, int tid)
{
#pragma unroll
    for (int i = 0; i < 8; i++) {
        int t = tid + (i << 7);
        int unit = t & 15, row = t >> 4;
        CPA16(smb + K_OFF + buf * KBUFB + row * 272 + unit * 16,
              khp + (long)(kv0 + row) * HD + unit * 8);
    }
#pragma unroll
    for (int i = 0; i < 8; i++) {
        int t = tid + (i << 7);
        int unit = t & 7, row = t >> 3;
        CPA16(smb + V_OFF + buf * VBUFB + row * 144 + unit * 16,
              vhp + (long)row * SEQ + kv0 + unit * 8);
    }
}

__global__ __launch_bounds__(128, 2)
void flash_k(const __half* __restrict__ qhg, const __half* __restrict__ khg,
             const __half* __restrict__ vhg, __half* __restrict__ oah)
{
    extern __shared__ char dsm[];
    const uint32_t smb = smem_u32(dsm);
    const int tid  = threadIdx.x;
    const int w    = tid >> 5;
    const int lane = tid & 31;
    const int z    = blockIdx.x;
    const int mb   = 31 - blockIdx.y;
    const int kvh  = z >> 3;
    const int m0   = mb << 6;
    const int nt   = mb + 1;

    const __half* qhp = qhg + ((long)z * SEQ + m0) * HD;
    const __half* khp = khg + (long)kvh * SEQ * HD;
    const __half* vhp = vhg + (long)kvh * HD * SEQ;

#pragma unroll
    for (int i = 0; i < 8; i++) {
        int t = tid + (i << 7);
        int unit = t & 15, row = t >> 4;
        CPA16(smb + row * 272 + unit * 16, qhp + (long)row * HD + unit * 8);
    }
    CPA_COMMIT();
    kv_prefetch(smb, 0, 0, khp, vhp, tid);
    CPA_COMMIT();

    CPA_WAIT1();
    __syncthreads();
    const uint32_t qa_h = smb + (uint32_t)((w << 4) + (lane & 15)) * 272 + ((lane >> 4) << 4);
    uint32_t qf[8][4];
#pragma unroll
    for (int j = 0; j < 8; j++)
        LDSM4(qf[j][0], qf[j][1], qf[j][2], qf[j][3], qa_h + j * 32);

    float o[16][4];
#pragma unroll
    for (int nb = 0; nb < 16; nb++)
#pragma unroll
        for (int q = 0; q < 4; q++) o[nb][q] = 0.f;
    float mr0 = -1e30f, mr1 = -1e30f, l0 = 0.f, l1 = 0.f;

    const int wrow = m0 + (w << 4);
    const uint32_t brow = (lane & 7) + ((lane >> 4) & 1) * 8;
    const uint32_t bko  = ((lane >> 3) & 1) << 4;

    int buf = 0;
    for (int it = 0; it < nt; it++) {
        if (it + 1 < nt) {
            kv_prefetch(smb, buf ^ 1, (it + 1) << 6, khp, vhp, tid);
            CPA_COMMIT();
            CPA_WAIT1();
        } else {
            CPA_WAIT0();
        }
        __syncthreads();

        const int kv0 = it << 6;
        {
            const uint32_t kb_h = smb + K_OFF + buf * KBUFB;
            const uint32_t vb_h = smb + V_OFF + buf * VBUFB;

            float s[8][4];
#pragma unroll
            for (int nb = 0; nb < 8; nb++)
#pragma unroll
                for (int q = 0; q < 4; q++) s[nb][q] = 0.f;

#pragma unroll
            for (int j = 0; j < 8; j++) {
#pragma unroll
                for (int g16 = 0; g16 < 4; g16++) {
                    uint32_t bh[4];
                    const uint32_t ba = (uint32_t)(g16 * 16 + brow) * 272 + bko + j * 32;
                    LDSM4(bh[0], bh[1], bh[2], bh[3], kb_h + ba);
                    MMA16816(s[2 * g16],     qf[j], bh);
                    MMA16816(s[2 * g16 + 1], qf[j], bh + 2);
                }
            }

            const int r0 = wrow + (lane >> 2);
            const int c0 = kv0 + ((lane & 3) << 1);
            if (kv0 + 63 > wrow) {
#pragma unroll
                for (int nb = 0; nb < 8; nb++) {
                    const int c = c0 + nb * 8;
                    if (c     > r0    ) s[nb][0] = -1e30f;
                    if (c + 1 > r0    ) s[nb][1] = -1e30f;
                    if (c     > r0 + 8) s[nb][2] = -1e30f;
                    if (c + 1 > r0 + 8) s[nb][3] = -1e30f;
                }
            }

            float tm0 = -1e30f, tm1 = -1e30f;
#pragma unroll
            for (int nb = 0; nb < 8; nb++) {
                tm0 = fmaxf(tm0, fmaxf(s[nb][0], s[nb][1]));
                tm1 = fmaxf(tm1, fmaxf(s[nb][2], s[nb][3]));
            }
            tm0 = fmaxf(tm0, __shfl_xor_sync(0xffffffffu, tm0, 1));
            tm0 = fmaxf(tm0, __shfl_xor_sync(0xffffffffu, tm0, 2));
            tm1 = fmaxf(tm1, __shfl_xor_sync(0xffffffffu, tm1, 1));
            tm1 = fmaxf(tm1, __shfl_xor_sync(0xffffffffu, tm1, 2));
            const float mn0 = fmaxf(mr0, tm0), mn1 = fmaxf(mr1, tm1);
            const float sf0 = exp2f((mr0 - mn0) * FC);
            const float sf1 = exp2f((mr1 - mn1) * FC);
            mr0 = mn0; mr1 = mn1;
            l0 *= sf0;  l1 *= sf1;
#pragma unroll
            for (int nb = 0; nb < 16; nb++) {
                o[nb][0] *= sf0; o[nb][1] *= sf0;
                o[nb][2] *= sf1; o[nb][3] *= sf1;
            }
            float rs0 = 0.f, rs1 = 0.f;
#pragma unroll
            for (int nb = 0; nb < 8; nb++) {
                s[nb][0] = exp2f((s[nb][0] - mn0) * FC); rs0 += s[nb][0];
                s[nb][1] = exp2f((s[nb][1] - mn0) * FC); rs0 += s[nb][1];
                s[nb][2] = exp2f((s[nb][2] - mn1) * FC); rs1 += s[nb][2];
                s[nb][3] = exp2f((s[nb][3] - mn1) * FC); rs1 += s[nb][3];
            }
            rs0 += __shfl_xor_sync(0xffffffffu, rs0, 1);
            rs0 += __shfl_xor_sync(0xffffffffu, rs0, 2);
            rs1 += __shfl_xor_sync(0xffffffffu, rs1, 1);
            rs1 += __shfl_xor_sync(0xffffffffu, rs1, 2);
            l0 += rs0; l1 += rs1;

#pragma unroll
            for (int j = 0; j < 4; j++) {
                uint32_t pha[4];
#pragma unroll
                for (int hq = 0; hq < 4; hq++) {
                    const int nb = 2 * j + (hq >> 1);
                    const int e  = (hq & 1) << 1;
                    __half2 h = __floats2half2_rn(s[nb][e], s[nb][e + 1]);
                    pha[hq] = *reinterpret_cast<uint32_t*>(&h);
                }
#pragma unroll
                for (int g16 = 0; g16 < 8; g16++) {
                    uint32_t bh[4];
                    const uint32_t ba = (uint32_t)(g16 * 16 + brow) * 144 + bko + j * 32;
                    LDSM4(bh[0], bh[1], bh[2], bh[3], vb_h + ba);
                    MMA16816(o[2 * g16],     pha, bh);
                    MMA16816(o[2 * g16 + 1], pha, bh + 2);
                }
            }
        }
        __syncthreads();
        buf ^= 1;
    }

    const float inv0 = 1.f / l0, inv1 = 1.f / l1;
    const int r0 = wrow + (lane >> 2);
    const long base0 = ((long)z * SEQ + r0) * HD + ((lane & 3) << 1);
    const long base1 = base0 + 8 * HD;
#pragma unroll
    for (int nb = 0; nb < 16; nb++) {
        *(__half2*)(oah + base0 + nb * 8) =
            __floats2half2_rn(o[nb][0] * inv0, o[nb][1] * inv0);
        *(__half2*)(oah + base1 + nb * 8) =
            __floats2half2_rn(o[nb][2] * inv1, o[nb][3] * inv1);
    }
}

// ---------------- prep: rope table + weight cvt in one launch ----------------
#define TAB_BLKS 512
__global__ __launch_bounds__(256)
void prep_k(const int* __restrict__ pos, float2* __restrict__ tab,
            const float* __restrict__ qw, const float* __restrict__ kw,
            const float* __restrict__ vw, const float* __restrict__ ow,
            __half* __restrict__ d)
{
    const int bid = blockIdx.x;
    if (bid < TAB_BLKS) {
        int idx = bid * 256 + threadIdx.x;
        if (idx >= SEQ * 64) return;
        int i = idx & 63;
        int l = idx >> 6;
        float invf = exp2f(-(float)i * 0.31143075889569023f);
        float ang  = (float)pos[l] * invf;
        float q  = rintf(ang * 0.15915494309189535f);
        float r  = ang - q * 6.28125f;
        r        = r   - q * 1.9353071795864769e-3f;
        float s, c;
        sincosf(r, &s, &c);
        tab[idx] = make_float2(c, s);
        return;
    }
    int e = ((bid - TAB_BLKS) * 256 + threadIdx.x) << 2;
    if (e >= W_TOT) return;
    const float* s;
    if      (e < KW_OFF) s = qw + e;
    else if (e < VW_OFF) s = kw + (e - KW_OFF);
    else if (e < OW_OFF) s = vw + (e - VW_OFF);
    else                 s = ow + (e - OW_OFF);
    float4 v = *(const float4*)s;
    ((__half2*)(d + e))[0] = __floats2half2_rn(v.x, v.y);
    ((__half2*)(d + e))[1] = __floats2half2_rn(v.z, v.w);
}

// ---------------- launch ----------------
extern "C" void kernel_launch(void* const* d_in, const int* in_sizes, int n_in,
                              void* d_out, int out_size)
{
    const float* qhid = (const float*)d_in[0];
    const float* khid = (const float*)d_in[1];
    const float* vhid = (const float*)d_in[2];
    const int*   pos  = (const int*)  d_in[4];
    const float* qw   = (const float*)d_in[5];
    const float* kw   = (const float*)d_in[6];
    const float* vw   = (const float*)d_in[7];
    const float* ow   = (const float*)d_in[8];
    float*       out  = (float*)d_out;

    __half *qhh, *khh, *vth, *ahh, *wh;
    float2* tab;
    cudaGetSymbolAddress((void**)&qhh, g_qh);
    cudaGetSymbolAddress((void**)&khh, g_kh);
    cudaGetSymbolAddress((void**)&vth, g_vth);
    cudaGetSymbolAddress((void**)&ahh, g_ah);
    cudaGetSymbolAddress((void**)&wh,  g_wh);
    cudaGetSymbolAddress((void**)&tab, g_tab);

    cudaFuncSetAttribute(proj_k,  cudaFuncAttributeMaxDynamicSharedMemorySize, PSMB);
    cudaFuncSetAttribute(oproj_k, cudaFuncAttributeMaxDynamicSharedMemorySize, OSMB);
    cudaFuncSetAttribute(flash_k, cudaFuncAttributeMaxDynamicSharedMemorySize, FSMEM);

    prep_k<<<TAB_BLKS + (W_TOT / 4 + 255) / 256, 256>>>(pos, tab, qw, kw, vw, ow, wh);
    proj_k<<<dim3(1, 32, NH + 2 * NKV), 256, PSMB>>>(qhid, khid, vhid, wh, tab);
    flash_k<<<dim3(NH, 32), 128, FSMEM>>>(qhh, khh, vth, ahh);
    oproj_k<<<dim3(4, 16, NH), 256, OSMB>>>(ahh, wh + OW_OFF, out);
}